// round 13
// baseline (speedup 1.0000x reference)
#include <cuda_runtime.h>
#include <cstdint>
#include <cstddef>

#define BSZ 8
#define SEQL 1024
#define DMODEL 1024
#define NH 16
#define DK 64
#define ATT_SCALE 0.125f   // 64^-0.5  (power of two -> exact prescale of q)

// Static scratch (allocation-free rule: __device__ globals)
__device__ float g_q[(size_t)BSZ*NH*SEQL*DK];    // [b,h,s,d] tf32-rounded, x0.125
__device__ float g_k[(size_t)BSZ*NH*SEQL*DK];    // tf32-rounded
__device__ float g_v[(size_t)BSZ*NH*SEQL*DK];    // tf32-rounded
__device__ float g_ctx[(size_t)BSZ*SEQL*DMODEL]; // [b,s,(h d)] tf32-rounded
__device__ float g_rowsum[(size_t)BSZ*NH*SEQL];  // sum of exp(scores) per row
// tf32-pre-rounded copies of inputs/weights (removes all inner-loop cvts)
__device__ float g_rq[(size_t)BSZ*SEQL*DMODEL];
__device__ float g_rk[(size_t)BSZ*SEQL*DMODEL];
__device__ float g_rv[(size_t)BSZ*SEQL*DMODEL];
__device__ float g_rwq[(size_t)DMODEL*DMODEL];
__device__ float g_rwk[(size_t)DMODEL*DMODEL];
__device__ float g_rwv[(size_t)DMODEL*DMODEL];
__device__ float g_rwo[(size_t)DMODEL*DMODEL];

enum { MODE_PROJ = 0, MODE_OUT = 3 };

__device__ __forceinline__ uint32_t tf32u(float x) {
    uint32_t u;
    asm("cvt.rna.tf32.f32 %0, %1;" : "=r"(u) : "f"(x));
    return u;
}
__device__ __forceinline__ float tf32f(float x) { return __uint_as_float(tf32u(x)); }

__device__ __forceinline__ void cp_async16(uint32_t smem_addr, const void* gptr) {
    asm volatile("cp.async.cg.shared.global [%0], [%1], 16;\n"
                 :: "r"(smem_addr), "l"(gptr));
}
__device__ __forceinline__ void cp_commit() {
    asm volatile("cp.async.commit_group;\n");
}
__device__ __forceinline__ void cp_wait0() {
    asm volatile("cp.async.wait_group 0;\n");
}

__device__ __forceinline__ void mma_tf32(float c[4], const uint32_t a[4], const uint32_t b[2]) {
    asm volatile(
        "mma.sync.aligned.m16n8k8.row.col.f32.tf32.tf32.f32 "
        "{%0,%1,%2,%3}, {%4,%5,%6,%7}, {%8,%9}, {%0,%1,%2,%3};"
        : "+f"(c[0]), "+f"(c[1]), "+f"(c[2]), "+f"(c[3])
        : "r"(a[0]), "r"(a[1]), "r"(a[2]), "r"(a[3]), "r"(b[0]), "r"(b[1]));
}

// ldmatrix x4: four 8x8 b16 tiles (= four 8x4 tf32 tiles), type-agnostic.
__device__ __forceinline__ void ldsm_x4(uint32_t a[4], uint32_t addr) {
    asm volatile("ldmatrix.sync.aligned.m8n8.x4.shared.b16 {%0,%1,%2,%3}, [%4];"
                 : "=r"(a[0]), "=r"(a[1]), "=r"(a[2]), "=r"(a[3]) : "r"(addr));
}

// Per-thread LDSM address components for the A-fragment pattern:
// tiles: [rows r..r+7, k..k+3], [r+8.., k..], [r.., k+4..], [r+8.., k+4..]
// lanes 0-7 -> tile0 rows, 8-15 -> tile1, 16-23 -> tile2, 24-31 -> tile3.
// arow = (lane&7) + ((lane>>3)&1)*8 ; acol = ((lane>>4)<<2)
// B-fragment (n-major smem Bs[c][k]) pattern for an nn-pair:
// tiles: [c..c+7, k..k+3], [c..c+7, k+4..], [c+8.., k..], [c+8.., k+4..]
// brow = (lane&7) + ((lane>>4)<<3) ; bcol = ((lane>>3)&1)*4

// ============================================================================
// Elementwise tf32-rounding copy (prep pass), float4-vectorized.
// ============================================================================
__global__ void __launch_bounds__(256) round_copy(
    const float4* __restrict__ in, float4* __restrict__ out, int n4)
{
    int i = blockIdx.x * 256 + threadIdx.x;
    if (i < n4) {
        float4 v = in[i];
        v.x = tf32f(v.x); v.y = tf32f(v.y); v.z = tf32f(v.z); v.w = tf32f(v.w);
        out[i] = v;
    }
}

// ============================================================================
// Big-K GEMM (K=1024): 128 threads, 4 warps, 64x64 warp tile, BK=32,
// 2-stage cp.async (2 CTAs/SM), A-fragments via ldmatrix.x4, B via LDS.32
// with register double-buffering. Operands PRE-ROUNDED tf32.
// C = (A@B + bias) * out_scale.
// ============================================================================
template <int MODE, bool ROUND_C>
__global__ void __launch_bounds__(128) gemm_big(
    const float* __restrict__ A, const float* __restrict__ B,
    const float* __restrict__ bias, float* __restrict__ C,
    int M, int N, int K, float out_scale)
{
    constexpr int BM = 128, BN = 128, BK = 32;
    constexpr int ASTR = BK + 4;   // 36 floats = 144B rows (16B aligned)
    constexpr int BSTR = BN + 8;   // 136
    __shared__ float As[2][BM * ASTR];
    __shared__ float Bs[2][BK * BSTR];

    const int tid  = threadIdx.x;
    const int lane = tid & 31;
    const int warp = tid >> 5;
    const int wm = (warp >> 1) * 64;
    const int wn = (warp & 1) * 64;
    const int m0 = blockIdx.y * BM;
    const int n0 = blockIdx.x * BN;

    const int arow = (lane & 7) + ((lane >> 3) & 1) * 8;
    const int acol = ((lane >> 4) << 2);

    constexpr int MMS = 4, MNS = 8;
    float acc[MMS][MNS][4];
    #pragma unroll
    for (int i = 0; i < MMS; i++)
        #pragma unroll
        for (int j = 0; j < MNS; j++)
            #pragma unroll
            for (int r = 0; r < 4; r++) acc[i][j][r] = 0.f;

    auto load_stage = [&](int st, int k0) {
        uint32_t abase = (uint32_t)__cvta_generic_to_shared(&As[st][0]);
        #pragma unroll
        for (int f = tid; f < BM * BK / 4; f += 128) {
            int row = f >> 3;            // BK/4 == 8
            int kg  = (f & 7) << 2;
            cp_async16(abase + (uint32_t)(row * ASTR + kg) * 4,
                       A + (size_t)(m0 + row) * K + k0 + kg);
        }
        uint32_t bbase = (uint32_t)__cvta_generic_to_shared(&Bs[st][0]);
        #pragma unroll
        for (int f = tid; f < BK * BN / 4; f += 128) {
            int kk = f >> 5;             // BN/4 == 32
            int ng = (f & 31) << 2;
            cp_async16(bbase + (uint32_t)(kk * BSTR + ng) * 4,
                       B + (size_t)(k0 + kk) * N + n0 + ng);
        }
        cp_commit();
    };

    auto compute_stage = [&](int st) {
        const float* __restrict__ Bsm = Bs[st];
        const uint32_t abase = (uint32_t)__cvta_generic_to_shared(&As[st][0]);
        uint32_t af[2][MMS][4];
        uint32_t bf[2][MNS][2];
        auto load_a = [&](int buf, int kk) {
            #pragma unroll
            for (int mm = 0; mm < MMS; mm++)
                ldsm_x4(af[buf][mm],
                        abase + (uint32_t)((wm + mm * 16 + arow) * ASTR + kk + acol) * 4);
        };
        auto load_b = [&](int buf, int kk) {
            const int kb = kk + (lane & 3);
            #pragma unroll
            for (int nn = 0; nn < MNS; nn++) {
                int c = wn + nn * 8 + (lane >> 2);
                bf[buf][nn][0] = __float_as_uint(Bsm[kb * BSTR + c]);
                bf[buf][nn][1] = __float_as_uint(Bsm[(kb + 4) * BSTR + c]);
            }
        };
        load_a(0, 0); load_b(0, 0);
        #pragma unroll
        for (int kk = 0; kk < BK; kk += 8) {
            int cur = (kk >> 3) & 1;
            if (kk + 8 < BK) { load_a(cur ^ 1, kk + 8); load_b(cur ^ 1, kk + 8); }
            #pragma unroll
            for (int mm = 0; mm < MMS; mm++)
                #pragma unroll
                for (int nn = 0; nn < MNS; nn++)
                    mma_tf32(acc[mm][nn], af[cur][mm], bf[cur][nn]);
        }
    };

    int stage = 0;
    load_stage(0, 0);
    cp_wait0();
    __syncthreads();
    for (int k0 = BK; k0 < K; k0 += BK) {
        load_stage(stage ^ 1, k0);
        compute_stage(stage);
        cp_wait0();
        __syncthreads();
        stage ^= 1;
    }
    compute_stage(stage);

    #pragma unroll
    for (int mm = 0; mm < MMS; mm++) {
        #pragma unroll
        for (int nn = 0; nn < MNS; nn++) {
            #pragma unroll
            for (int half = 0; half < 2; half++) {
                int row = m0 + wm + mm * 16 + (lane >> 2) + half * 8;
                int col = n0 + wn + nn * 8 + ((lane & 3) << 1);
                float v0 = (acc[mm][nn][half * 2 + 0] + bias[col])     * out_scale;
                float v1 = (acc[mm][nn][half * 2 + 1] + bias[col + 1]) * out_scale;
                if (ROUND_C) { v0 = tf32f(v0); v1 = tf32f(v1); }
                if (MODE == MODE_PROJ) {
                    int b = row >> 10, s = row & (SEQL - 1);
                    int h = col >> 6,  d = col & (DK - 1);
                    *reinterpret_cast<float2*>(
                        &C[((size_t)(b * NH + h) * SEQL + s) * DK + d]) =
                        make_float2(v0, v1);
                } else {
                    *reinterpret_cast<float2*>(&C[(size_t)row * DMODEL + col]) =
                        make_float2(v0, v1);
                }
            }
        }
    }
}

// ============================================================================
// Scores: per z=(b,h), scores = q_scaled @ k^T (q carries the 1/8 scale).
// Both operands pre-rounded tf32 and n/k-major in smem -> LDSM on A and B.
// Epilogue stores scores + exp-rowsums (atomics).
// ============================================================================
__global__ void __launch_bounds__(256, 2) scores_kernel(
    const float* __restrict__ qroot, const float* __restrict__ kroot,
    float* __restrict__ scores, float* __restrict__ rowsum)
{
    constexpr int BM = 128, BN = 128, STR = DK + 4;  // 68 floats = 272B (16B aligned)
    const int z = blockIdx.z;
    const float* A = qroot + (size_t)z * SEQL * DK;
    const float* B = kroot + (size_t)z * SEQL * DK;

    __shared__ float As[BM * STR];
    __shared__ float Bs[BN * STR];

    const int tid  = threadIdx.x;
    const int lane = tid & 31;
    const int warp = tid >> 5;
    const int wm = (warp >> 1) * 32;
    const int wn = (warp & 1) * 64;
    const int m0 = blockIdx.y * BM;
    const int n0 = blockIdx.x * BN;

    const int arow = (lane & 7) + ((lane >> 3) & 1) * 8;
    const int acol = ((lane >> 4) << 2);
    const int brow = (lane & 7) + ((lane >> 4) << 3);
    const int bcol = ((lane >> 3) & 1) * 4;

    {
        uint32_t abase = (uint32_t)__cvta_generic_to_shared(&As[0]);
        uint32_t bbase = (uint32_t)__cvta_generic_to_shared(&Bs[0]);
        #pragma unroll
        for (int f = tid; f < BM * DK / 4; f += 256) {
            int row = f >> 4;            // DK/4 == 16
            int kg  = (f & 15) << 2;
            cp_async16(abase + (uint32_t)(row * STR + kg) * 4,
                       A + (size_t)(m0 + row) * DK + kg);
            cp_async16(bbase + (uint32_t)(row * STR + kg) * 4,
                       B + (size_t)(n0 + row) * DK + kg);
        }
        cp_commit();
        cp_wait0();
        __syncthreads();
    }

    constexpr int MMS = 2, MNS = 8;
    float acc[MMS][MNS][4];
    #pragma unroll
    for (int i = 0; i < MMS; i++)
        #pragma unroll
        for (int j = 0; j < MNS; j++)
            #pragma unroll
            for (int r = 0; r < 4; r++) acc[i][j][r] = 0.f;

    {
        const uint32_t abase = (uint32_t)__cvta_generic_to_shared(&As[0]);
        const uint32_t bbase = (uint32_t)__cvta_generic_to_shared(&Bs[0]);
        uint32_t af[2][MMS][4];
        uint32_t bf[2][MNS][2];
        auto load_frags = [&](int buf, int kk) {
            #pragma unroll
            for (int mm = 0; mm < MMS; mm++)
                ldsm_x4(af[buf][mm],
                        abase + (uint32_t)((wm + mm * 16 + arow) * STR + kk + acol) * 4);
            #pragma unroll
            for (int np = 0; np < MNS / 2; np++) {
                uint32_t t[4];
                ldsm_x4(t, bbase + (uint32_t)((wn + np * 16 + brow) * STR + kk + bcol) * 4);
                bf[buf][np * 2 + 0][0] = t[0];
                bf[buf][np * 2 + 0][1] = t[1];
                bf[buf][np * 2 + 1][0] = t[2];
                bf[buf][np * 2 + 1][1] = t[3];
            }
        };
        load_frags(0, 0);
        #pragma unroll
        for (int kk = 0; kk < DK; kk += 8) {
            int cur = (kk >> 3) & 1;
            if (kk + 8 < DK) load_frags(cur ^ 1, kk + 8);
            #pragma unroll
            for (int mm = 0; mm < MMS; mm++)
                #pragma unroll
                for (int nn = 0; nn < MNS; nn++)
                    mma_tf32(acc[mm][nn], af[cur][mm], bf[cur][nn]);
        }
    }

    float esum[MMS][2];
    #pragma unroll
    for (int mm = 0; mm < MMS; mm++) { esum[mm][0] = 0.f; esum[mm][1] = 0.f; }

    #pragma unroll
    for (int mm = 0; mm < MMS; mm++) {
        #pragma unroll
        for (int nn = 0; nn < MNS; nn++) {
            #pragma unroll
            for (int half = 0; half < 2; half++) {
                int row = m0 + wm + mm * 16 + (lane >> 2) + half * 8;
                int col = n0 + wn + nn * 8 + ((lane & 3) << 1);
                float v0 = acc[mm][nn][half * 2 + 0];
                float v1 = acc[mm][nn][half * 2 + 1];
                *reinterpret_cast<float2*>(
                    &scores[(size_t)z * SEQL * SEQL + (size_t)row * SEQL + col]) =
                    make_float2(v0, v1);
                esum[mm][half] += __expf(v0) + __expf(v1);
            }
        }
    }
    #pragma unroll
    for (int mm = 0; mm < MMS; mm++) {
        #pragma unroll
        for (int half = 0; half < 2; half++) {
            float s = esum[mm][half];
            s += __shfl_xor_sync(~0u, s, 1);
            s += __shfl_xor_sync(~0u, s, 2);
            if ((lane & 3) == 0) {
                int row = m0 + wm + mm * 16 + (lane >> 2) + half * 8;
                atomicAdd(&rowsum[(size_t)z * SEQL + row], s);
            }
        }
    }
}

// ============================================================================
// Fused softmax + PV: per z=(b,h). 2-stage cp.async (2 CTAs/SM).
// transform computes w = exp(s)*inv_rowsum, writes exact fp32 w to gmem
// weights, stores tf32-rounded w into smem -> A-side LDSM, no cvt in MMA loop.
// ctx = w @ v. BK=32.
// ============================================================================
__global__ void __launch_bounds__(256, 2) pv_fused(
    const float* __restrict__ scores, const float* __restrict__ vroot,
    const float* __restrict__ rowsum,
    float* __restrict__ weights, float* __restrict__ ctx)
{
    constexpr int BM = 128, BN = 64, BK = 32;
    constexpr int ASTR = BK + 4;   // 36 floats = 144B (16B aligned)
    constexpr int BSTR = BN + 8;   // 72
    const int z = blockIdx.z;
    const float* A = scores + (size_t)z * SEQL * SEQL;   // [1024,1024]
    const float* B = vroot  + (size_t)z * SEQL * DK;     // [1024,64]

    __shared__ float As[2][BM * ASTR];
    __shared__ float Bs[2][BK * BSTR];
    __shared__ float inv_s[BM];

    const int tid  = threadIdx.x;
    const int lane = tid & 31;
    const int warp = tid >> 5;
    const int wm = (warp >> 1) * 32;
    const int wn = (warp & 1) * 32;
    const int m0 = blockIdx.y * BM;

    const int arow = (lane & 7) + ((lane >> 3) & 1) * 8;
    const int acol = ((lane >> 4) << 2);

    if (tid < BM)
        inv_s[tid] = 1.0f / rowsum[(size_t)z * SEQL + m0 + tid];

    constexpr int MMS = 2, MNS = 4;
    float acc[MMS][MNS][4];
    #pragma unroll
    for (int i = 0; i < MMS; i++)
        #pragma unroll
        for (int j = 0; j < MNS; j++)
            #pragma unroll
            for (int r = 0; r < 4; r++) acc[i][j][r] = 0.f;

    auto load_stage = [&](int st, int k0) {
        uint32_t abase = (uint32_t)__cvta_generic_to_shared(&As[st][0]);
        #pragma unroll
        for (int f = tid; f < BM * BK / 4; f += 256) {
            int row = f >> 3;            // BK/4 == 8
            int kg  = (f & 7) << 2;
            cp_async16(abase + (uint32_t)(row * ASTR + kg) * 4,
                       A + (size_t)(m0 + row) * SEQL + k0 + kg);
        }
        uint32_t bbase = (uint32_t)__cvta_generic_to_shared(&Bs[st][0]);
        #pragma unroll
        for (int f = tid; f < BK * BN / 4; f += 256) {
            int kk = f >> 4;             // BN/4 == 16
            int ng = (f & 15) << 2;
            cp_async16(bbase + (uint32_t)(kk * BSTR + ng) * 4,
                       B + (size_t)(k0 + kk) * DK + ng);
        }
        cp_commit();
    };

    // exp + normalize; gmem gets exact fp32 w, smem gets tf32-rounded w
    auto transform_stage = [&](int st, int k0) {
        float* Asm = As[st];
        #pragma unroll
        for (int f = tid; f < BM * BK / 4; f += 256) {
            int row = f >> 3;
            int kg  = (f & 7) << 2;
            float* p = &Asm[row * ASTR + kg];
            float inv = inv_s[row];
            float w0 = __expf(p[0]) * inv;
            float w1 = __expf(p[1]) * inv;
            float w2 = __expf(p[2]) * inv;
            float w3 = __expf(p[3]) * inv;
            *reinterpret_cast<float4*>(
                &weights[(size_t)z * SEQL * SEQL + (size_t)(m0 + row) * SEQL + k0 + kg]) =
                make_float4(w0, w1, w2, w3);
            p[0] = tf32f(w0); p[1] = tf32f(w1); p[2] = tf32f(w2); p[3] = tf32f(w3);
        }
    };

    auto compute_stage = [&](int st) {
        const float* __restrict__ Bsm = Bs[st];
        const uint32_t abase = (uint32_t)__cvta_generic_to_shared(&As[st][0]);
        #pragma unroll
        for (int kk = 0; kk < BK; kk += 8) {
            const int kb = kk + (lane & 3);
            uint32_t af[MMS][4];
            #pragma unroll
            for (int mm = 0; mm < MMS; mm++)
                ldsm_x4(af[mm],
                        abase + (uint32_t)((wm + mm * 16 + arow) * ASTR + kk + acol) * 4);
            uint32_t bf[MNS][2];
            #pragma unroll
            for (int nn = 0; nn < MNS; nn++) {
                int c = wn + nn * 8 + (lane >> 2);
                bf[nn][0] = __float_as_uint(Bsm[kb * BSTR + c]);      // v pre-rounded
                bf[nn][1] = __float_as_uint(Bsm[(kb + 4) * BSTR + c]);
            }
            #pragma unroll
            for (int mm = 0; mm < MMS; mm++)
                #pragma unroll
                for (int nn = 0; nn < MNS; nn++)
                    mma_tf32(acc[mm][nn], af[mm], bf[nn]);
        }
    };

    int stage = 0;
    load_stage(0, 0);
    cp_wait0();
    __syncthreads();           // stage0 data + inv_s ready
    for (int k0 = BK; k0 < SEQL; k0 += BK) {
        load_stage(stage ^ 1, k0);          // prefetch into other buffer
        transform_stage(stage, k0 - BK);    // exp/normalize current, write weights
        __syncthreads();                    // transformed smem visible
        compute_stage(stage);
        cp_wait0();
        __syncthreads();
        stage ^= 1;
    }
    transform_stage(stage, SEQL - BK);
    __syncthreads();
    compute_stage(stage);

    // epilogue: ctx [b, s, (h d)], tf32-rounded for the out-GEMM
    const int b = z >> 4, h = z & (NH - 1);
    #pragma unroll
    for (int mm = 0; mm < MMS; mm++) {
        #pragma unroll
        for (int nn = 0; nn < MNS; nn++) {
            #pragma unroll
            for (int half = 0; half < 2; half++) {
                int row = m0 + wm + mm * 16 + (lane >> 2) + half * 8;
                int col = wn + nn * 8 + ((lane & 3) << 1);
                *reinterpret_cast<float2*>(
                    &ctx[(size_t)(b * SEQL + row) * DMODEL + h * DK + col]) =
                    make_float2(tf32f(acc[mm][nn][half * 2 + 0]),
                                tf32f(acc[mm][nn][half * 2 + 1]));
            }
        }
    }
}

extern "C" void kernel_launch(void* const* d_in, const int* in_sizes, int n_in,
                              void* d_out, int out_size)
{
    const float* Q   = (const float*)d_in[0];
    const float* K   = (const float*)d_in[1];
    const float* V   = (const float*)d_in[2];
    const float* WQw = (const float*)d_in[3];
    const float* WQb = (const float*)d_in[4];
    const float* WKw = (const float*)d_in[5];
    const float* WKb = (const float*)d_in[6];
    const float* WVw = (const float*)d_in[7];
    const float* WVb = (const float*)d_in[8];
    const float* Wow = (const float*)d_in[9];
    const float* Wob = (const float*)d_in[10];

    float* out     = (float*)d_out;                              // [8,1024,1024]
    float* weights = out + (size_t)BSZ * SEQL * DMODEL;          // [8,16,1024,1024]
    float* scores  = weights + (size_t)BSZ * NH * SEQL * SEQL;   // [8,16,1024,1024]

    float *qp, *kp, *vp, *cp, *rs;
    float *rq, *rk, *rv, *rwq, *rwk, *rwv, *rwo;
    cudaGetSymbolAddress((void**)&qp, g_q);
    cudaGetSymbolAddress((void**)&kp, g_k);
    cudaGetSymbolAddress((void**)&vp, g_v);
    cudaGetSymbolAddress((void**)&cp, g_ctx);
    cudaGetSymbolAddress((void**)&rs, g_rowsum);
    cudaGetSymbolAddress((void**)&rq, g_rq);
    cudaGetSymbolAddress((void**)&rk, g_rk);
    cudaGetSymbolAddress((void**)&rv, g_rv);
    cudaGetSymbolAddress((void**)&rwq, g_rwq);
    cudaGetSymbolAddress((void**)&rwk, g_rwk);
    cudaGetSymbolAddress((void**)&rwv, g_rwv);
    cudaGetSymbolAddress((void**)&rwo, g_rwo);

    const int M = BSZ * SEQL;  // 8192

    cudaMemsetAsync(rs, 0, (size_t)BSZ * NH * SEQL * sizeof(float));

    // Prep: tf32-round inputs and weights once (removes all inner-loop cvts)
    const int nx4 = (BSZ * SEQL * DMODEL) / 4;     // 2M float4
    const int nw4 = (DMODEL * DMODEL) / 4;         // 256K float4
    round_copy<<<nx4 / 256, 256>>>((const float4*)Q,   (float4*)rq,  nx4);
    round_copy<<<nx4 / 256, 256>>>((const float4*)K,   (float4*)rk,  nx4);
    round_copy<<<nx4 / 256, 256>>>((const float4*)V,   (float4*)rv,  nx4);
    round_copy<<<nw4 / 256, 256>>>((const float4*)WQw, (float4*)rwq, nw4);
    round_copy<<<nw4 / 256, 256>>>((const float4*)WKw, (float4*)rwk, nw4);
    round_copy<<<nw4 / 256, 256>>>((const float4*)WVw, (float4*)rwv, nw4);
    round_copy<<<nw4 / 256, 256>>>((const float4*)Wow, (float4*)rwo, nw4);

    // QKV projections -> [b,h,s,d]; q carries ATT_SCALE; outputs tf32-rounded
    gemm_big<MODE_PROJ, true><<<dim3(DMODEL/128, M/128), 128>>>(rq, rwq, WQb, qp, M, DMODEL, DMODEL, ATT_SCALE);
    gemm_big<MODE_PROJ, true><<<dim3(DMODEL/128, M/128), 128>>>(rk, rwk, WKb, kp, M, DMODEL, DMODEL, 1.0f);
    gemm_big<MODE_PROJ, true><<<dim3(DMODEL/128, M/128), 128>>>(rv, rwv, WVb, vp, M, DMODEL, DMODEL, 1.0f);

    // attn_scores = q_scaled @ k^T ; accumulate per-row exp-sums
    scores_kernel<<<dim3(SEQL/128, SEQL/128, BSZ*NH), 256>>>(qp, kp, scores, rs);

    // attn_weights = exp(scores)/rowsum (written inside), ctx = weights @ v
    pv_fused<<<dim3(1, SEQL/128, BSZ*NH), 256>>>(scores, vp, rs, weights, cp);

    // output = ctx @ Wo + b  (both operands pre-rounded)
    gemm_big<MODE_OUT, false><<<dim3(DMODEL/128, M/128), 128>>>(cp, rwo, Wob, out, M, DMODEL, DMODEL, 1.0f);
}

// round 14
// speedup vs baseline: 1.0272x; 1.0272x over previous
#include <cuda_runtime.h>
#include <cstdint>
#include <cstddef>

#define BSZ 8
#define SEQL 1024
#define DMODEL 1024
#define NH 16
#define DK 64
#define ATT_SCALE 0.125f   // 64^-0.5  (power of two -> exact prescale of q)

// Static scratch (allocation-free rule: __device__ globals)
__device__ float g_q[(size_t)BSZ*NH*SEQL*DK];    // [b,h,s,d] tf32-rounded, x0.125
__device__ float g_k[(size_t)BSZ*NH*SEQL*DK];    // tf32-rounded
__device__ float g_v[(size_t)BSZ*NH*SEQL*DK];    // tf32-rounded
__device__ float g_ctx[(size_t)BSZ*SEQL*DMODEL]; // [b,s,(h d)] tf32-rounded
__device__ float g_rowsum[(size_t)BSZ*NH*SEQL];  // sum of exp(scores) per row
// tf32-pre-rounded copies of inputs/weights (removes all inner-loop cvts)
__device__ float g_rq[(size_t)BSZ*SEQL*DMODEL];
__device__ float g_rk[(size_t)BSZ*SEQL*DMODEL];
__device__ float g_rv[(size_t)BSZ*SEQL*DMODEL];
__device__ float g_rwq[(size_t)DMODEL*DMODEL];
__device__ float g_rwk[(size_t)DMODEL*DMODEL];
__device__ float g_rwv[(size_t)DMODEL*DMODEL];
__device__ float g_rwo[(size_t)DMODEL*DMODEL];

enum { MODE_PROJ = 0, MODE_OUT = 3 };

__device__ __forceinline__ uint32_t tf32u(float x) {
    uint32_t u;
    asm("cvt.rna.tf32.f32 %0, %1;" : "=r"(u) : "f"(x));
    return u;
}
__device__ __forceinline__ float tf32f(float x) { return __uint_as_float(tf32u(x)); }

__device__ __forceinline__ void cp_async16(uint32_t smem_addr, const void* gptr) {
    asm volatile("cp.async.cg.shared.global [%0], [%1], 16;\n"
                 :: "r"(smem_addr), "l"(gptr));
}
__device__ __forceinline__ void cp_commit() {
    asm volatile("cp.async.commit_group;\n");
}
__device__ __forceinline__ void cp_wait0() {
    asm volatile("cp.async.wait_group 0;\n");
}
__device__ __forceinline__ void cp_wait1() {
    asm volatile("cp.async.wait_group 1;\n");
}

__device__ __forceinline__ void mma_tf32(float c[4], const uint32_t a[4], const uint32_t b[2]) {
    asm volatile(
        "mma.sync.aligned.m16n8k8.row.col.f32.tf32.tf32.f32 "
        "{%0,%1,%2,%3}, {%4,%5,%6,%7}, {%8,%9}, {%0,%1,%2,%3};"
        : "+f"(c[0]), "+f"(c[1]), "+f"(c[2]), "+f"(c[3])
        : "r"(a[0]), "r"(a[1]), "r"(a[2]), "r"(a[3]), "r"(b[0]), "r"(b[1]));
}

// ldmatrix x4: four 8x8 b16 tiles (= four 8x4 tf32 tiles), type-agnostic.
__device__ __forceinline__ void ldsm_x4(uint32_t a[4], uint32_t addr) {
    asm volatile("ldmatrix.sync.aligned.m8n8.x4.shared.b16 {%0,%1,%2,%3}, [%4];"
                 : "=r"(a[0]), "=r"(a[1]), "=r"(a[2]), "=r"(a[3]) : "r"(addr));
}
// A-fragment LDSM lane mapping: arow=(lane&7)+((lane>>3)&1)*8 ; acol=((lane>>4)<<2)
// B-fragment (n-major) mapping:  brow=(lane&7)+((lane>>4)<<3) ; bcol=((lane>>3)&1)*4

// ============================================================================
// Elementwise tf32-rounding copy (prep pass), float4-vectorized.
// ============================================================================
__global__ void __launch_bounds__(256) round_copy(
    const float4* __restrict__ in, float4* __restrict__ out, int n4)
{
    int i = blockIdx.x * 256 + threadIdx.x;
    if (i < n4) {
        float4 v = in[i];
        v.x = tf32f(v.x); v.y = tf32f(v.y); v.z = tf32f(v.z); v.w = tf32f(v.w);
        out[i] = v;
    }
}

// ============================================================================
// Big-K GEMM (K=1024): 128 threads, 4 warps, 64x64 warp tile, BK=32,
// THREE-stage cp.async pipeline + register fragment double-buffering
// (exact R12 configuration — proven fastest for these launches).
// Operands PRE-ROUNDED tf32 (no inner cvt). C = (A@B + bias) * out_scale.
// ============================================================================
template <int MODE, bool ROUND_C>
__global__ void __launch_bounds__(128) gemm_big(
    const float* __restrict__ A, const float* __restrict__ B,
    const float* __restrict__ bias, float* __restrict__ C,
    int M, int N, int K, float out_scale)
{
    constexpr int BM = 128, BN = 128, BK = 32;
    constexpr int ASTR = BK + 4;   // 36
    constexpr int BSTR = BN + 8;   // 136
    __shared__ float As[3][BM * ASTR];
    __shared__ float Bs[3][BK * BSTR];

    const int tid  = threadIdx.x;
    const int lane = tid & 31;
    const int warp = tid >> 5;
    const int wm = (warp >> 1) * 64;
    const int wn = (warp & 1) * 64;
    const int m0 = blockIdx.y * BM;
    const int n0 = blockIdx.x * BN;

    constexpr int MMS = 4, MNS = 8;
    float acc[MMS][MNS][4];
    #pragma unroll
    for (int i = 0; i < MMS; i++)
        #pragma unroll
        for (int j = 0; j < MNS; j++)
            #pragma unroll
            for (int r = 0; r < 4; r++) acc[i][j][r] = 0.f;

    auto load_stage = [&](int st, int k0) {
        uint32_t abase = (uint32_t)__cvta_generic_to_shared(&As[st][0]);
        #pragma unroll
        for (int f = tid; f < BM * BK / 4; f += 128) {
            int row = f >> 3;            // BK/4 == 8
            int kg  = (f & 7) << 2;
            cp_async16(abase + (uint32_t)(row * ASTR + kg) * 4,
                       A + (size_t)(m0 + row) * K + k0 + kg);
        }
        uint32_t bbase = (uint32_t)__cvta_generic_to_shared(&Bs[st][0]);
        #pragma unroll
        for (int f = tid; f < BK * BN / 4; f += 128) {
            int kk = f >> 5;             // BN/4 == 32
            int ng = (f & 31) << 2;
            cp_async16(bbase + (uint32_t)(kk * BSTR + ng) * 4,
                       B + (size_t)(k0 + kk) * N + n0 + ng);
        }
        cp_commit();
    };

    auto compute_stage = [&](int st) {
        const float* __restrict__ Asm = As[st];
        const float* __restrict__ Bsm = Bs[st];
        uint32_t af[2][MMS][4];
        uint32_t bf[2][MNS][2];
        auto load_frags = [&](int buf, int kk) {
            const int kb = kk + (lane & 3);
            #pragma unroll
            for (int mm = 0; mm < MMS; mm++) {
                int r = wm + mm * 16 + (lane >> 2);
                af[buf][mm][0] = __float_as_uint(Asm[r * ASTR + kb]);
                af[buf][mm][1] = __float_as_uint(Asm[(r + 8) * ASTR + kb]);
                af[buf][mm][2] = __float_as_uint(Asm[r * ASTR + kb + 4]);
                af[buf][mm][3] = __float_as_uint(Asm[(r + 8) * ASTR + kb + 4]);
            }
            #pragma unroll
            for (int nn = 0; nn < MNS; nn++) {
                int c = wn + nn * 8 + (lane >> 2);
                bf[buf][nn][0] = __float_as_uint(Bsm[kb * BSTR + c]);
                bf[buf][nn][1] = __float_as_uint(Bsm[(kb + 4) * BSTR + c]);
            }
        };
        load_frags(0, 0);
        #pragma unroll
        for (int kk = 0; kk < BK; kk += 8) {
            int cur = (kk >> 3) & 1;
            if (kk + 8 < BK) load_frags(cur ^ 1, kk + 8);
            #pragma unroll
            for (int mm = 0; mm < MMS; mm++)
                #pragma unroll
                for (int nn = 0; nn < MNS; nn++)
                    mma_tf32(acc[mm][nn], af[cur][mm], bf[cur][nn]);
        }
    };

    // 3-stage pipeline
    int stage = 0;
    load_stage(0, 0);
    load_stage(1, BK);
    cp_wait1();
    __syncthreads();
    for (int k0 = 2 * BK; k0 < K; k0 += BK) {
        int s2 = stage + 2; if (s2 >= 3) s2 -= 3;
        load_stage(s2, k0);
        compute_stage(stage);
        cp_wait1();
        __syncthreads();
        stage = (stage + 1 == 3) ? 0 : stage + 1;
    }
    compute_stage(stage);
    cp_wait0();
    __syncthreads();
    stage = (stage + 1 == 3) ? 0 : stage + 1;
    compute_stage(stage);

    #pragma unroll
    for (int mm = 0; mm < MMS; mm++) {
        #pragma unroll
        for (int nn = 0; nn < MNS; nn++) {
            #pragma unroll
            for (int half = 0; half < 2; half++) {
                int row = m0 + wm + mm * 16 + (lane >> 2) + half * 8;
                int col = n0 + wn + nn * 8 + ((lane & 3) << 1);
                float v0 = (acc[mm][nn][half * 2 + 0] + bias[col])     * out_scale;
                float v1 = (acc[mm][nn][half * 2 + 1] + bias[col + 1]) * out_scale;
                if (ROUND_C) { v0 = tf32f(v0); v1 = tf32f(v1); }
                if (MODE == MODE_PROJ) {
                    int b = row >> 10, s = row & (SEQL - 1);
                    int h = col >> 6,  d = col & (DK - 1);
                    *reinterpret_cast<float2*>(
                        &C[((size_t)(b * NH + h) * SEQL + s) * DK + d]) =
                        make_float2(v0, v1);
                } else {
                    *reinterpret_cast<float2*>(&C[(size_t)row * DMODEL + col]) =
                        make_float2(v0, v1);
                }
            }
        }
    }
}

// ============================================================================
// Scores: per z=(b,h), scores = q_scaled @ k^T (q carries the 1/8 scale).
// Both operands pre-rounded tf32 and k-major in smem -> LDSM on A and B.
// Epilogue stores scores + exp-rowsums (atomics).
// ============================================================================
__global__ void __launch_bounds__(256, 2) scores_kernel(
    const float* __restrict__ qroot, const float* __restrict__ kroot,
    float* __restrict__ scores, float* __restrict__ rowsum)
{
    constexpr int BM = 128, BN = 128, STR = DK + 4;  // 68 floats = 272B (16B aligned)
    const int z = blockIdx.z;
    const float* A = qroot + (size_t)z * SEQL * DK;
    const float* B = kroot + (size_t)z * SEQL * DK;

    __shared__ float As[BM * STR];
    __shared__ float Bs[BN * STR];

    const int tid  = threadIdx.x;
    const int lane = tid & 31;
    const int warp = tid >> 5;
    const int wm = (warp >> 1) * 32;
    const int wn = (warp & 1) * 64;
    const int m0 = blockIdx.y * BM;
    const int n0 = blockIdx.x * BN;

    const int arow = (lane & 7) + ((lane >> 3) & 1) * 8;
    const int acol = ((lane >> 4) << 2);
    const int brow = (lane & 7) + ((lane >> 4) << 3);
    const int bcol = ((lane >> 3) & 1) * 4;

    {
        uint32_t abase = (uint32_t)__cvta_generic_to_shared(&As[0]);
        uint32_t bbase = (uint32_t)__cvta_generic_to_shared(&Bs[0]);
        #pragma unroll
        for (int f = tid; f < BM * DK / 4; f += 256) {
            int row = f >> 4;            // DK/4 == 16
            int kg  = (f & 15) << 2;
            cp_async16(abase + (uint32_t)(row * STR + kg) * 4,
                       A + (size_t)(m0 + row) * DK + kg);
            cp_async16(bbase + (uint32_t)(row * STR + kg) * 4,
                       B + (size_t)(n0 + row) * DK + kg);
        }
        cp_commit();
        cp_wait0();
        __syncthreads();
    }

    constexpr int MMS = 2, MNS = 8;
    float acc[MMS][MNS][4];
    #pragma unroll
    for (int i = 0; i < MMS; i++)
        #pragma unroll
        for (int j = 0; j < MNS; j++)
            #pragma unroll
            for (int r = 0; r < 4; r++) acc[i][j][r] = 0.f;

    {
        const uint32_t abase = (uint32_t)__cvta_generic_to_shared(&As[0]);
        const uint32_t bbase = (uint32_t)__cvta_generic_to_shared(&Bs[0]);
        uint32_t af[2][MMS][4];
        uint32_t bf[2][MNS][2];
        auto load_frags = [&](int buf, int kk) {
            #pragma unroll
            for (int mm = 0; mm < MMS; mm++)
                ldsm_x4(af[buf][mm],
                        abase + (uint32_t)((wm + mm * 16 + arow) * STR + kk + acol) * 4);
            #pragma unroll
            for (int np = 0; np < MNS / 2; np++) {
                uint32_t t[4];
                ldsm_x4(t, bbase + (uint32_t)((wn + np * 16 + brow) * STR + kk + bcol) * 4);
                bf[buf][np * 2 + 0][0] = t[0];
                bf[buf][np * 2 + 0][1] = t[1];
                bf[buf][np * 2 + 1][0] = t[2];
                bf[buf][np * 2 + 1][1] = t[3];
            }
        };
        load_frags(0, 0);
        #pragma unroll
        for (int kk = 0; kk < DK; kk += 8) {
            int cur = (kk >> 3) & 1;
            if (kk + 8 < DK) load_frags(cur ^ 1, kk + 8);
            #pragma unroll
            for (int mm = 0; mm < MMS; mm++)
                #pragma unroll
                for (int nn = 0; nn < MNS; nn++)
                    mma_tf32(acc[mm][nn], af[cur][mm], bf[cur][nn]);
        }
    }

    float esum[MMS][2];
    #pragma unroll
    for (int mm = 0; mm < MMS; mm++) { esum[mm][0] = 0.f; esum[mm][1] = 0.f; }

    #pragma unroll
    for (int mm = 0; mm < MMS; mm++) {
        #pragma unroll
        for (int nn = 0; nn < MNS; nn++) {
            #pragma unroll
            for (int half = 0; half < 2; half++) {
                int row = m0 + wm + mm * 16 + (lane >> 2) + half * 8;
                int col = n0 + wn + nn * 8 + ((lane & 3) << 1);
                float v0 = acc[mm][nn][half * 2 + 0];
                float v1 = acc[mm][nn][half * 2 + 1];
                *reinterpret_cast<float2*>(
                    &scores[(size_t)z * SEQL * SEQL + (size_t)row * SEQL + col]) =
                    make_float2(v0, v1);
                esum[mm][half] += __expf(v0) + __expf(v1);
            }
        }
    }
    #pragma unroll
    for (int mm = 0; mm < MMS; mm++) {
        #pragma unroll
        for (int half = 0; half < 2; half++) {
            float s = esum[mm][half];
            s += __shfl_xor_sync(~0u, s, 1);
            s += __shfl_xor_sync(~0u, s, 2);
            if ((lane & 3) == 0) {
                int row = m0 + wm + mm * 16 + (lane >> 2) + half * 8;
                atomicAdd(&rowsum[(size_t)z * SEQL + row], s);
            }
        }
    }
}

// ============================================================================
// Fused softmax + PV: per z=(b,h). 3-stage cp.async pipeline (wait_group 1).
// transform computes w = exp(s)*inv_rowsum, writes exact fp32 w to gmem
// weights, stores tf32-rounded w into smem -> A-side LDSM, no cvt in MMA loop.
// ctx = w @ v. BK=32.
// ============================================================================
__global__ void __launch_bounds__(256, 2) pv_fused(
    const float* __restrict__ scores, const float* __restrict__ vroot,
    const float* __restrict__ rowsum,
    float* __restrict__ weights, float* __restrict__ ctx)
{
    constexpr int BM = 128, BN = 64, BK = 32;
    constexpr int ASTR = BK + 4;   // 36 floats = 144B (16B aligned)
    constexpr int BSTR = BN + 8;   // 72
    const int z = blockIdx.z;
    const float* A = scores + (size_t)z * SEQL * SEQL;   // [1024,1024]
    const float* B = vroot  + (size_t)z * SEQL * DK;     // [1024,64]

    __shared__ float As[3][BM * ASTR];
    __shared__ float Bs[3][BK * BSTR];
    __shared__ float inv_s[BM];

    const int tid  = threadIdx.x;
    const int lane = tid & 31;
    const int warp = tid >> 5;
    const int wm = (warp >> 1) * 32;
    const int wn = (warp & 1) * 32;
    const int m0 = blockIdx.y * BM;

    const int arow = (lane & 7) + ((lane >> 3) & 1) * 8;
    const int acol = ((lane >> 4) << 2);

    if (tid < BM)
        inv_s[tid] = 1.0f / rowsum[(size_t)z * SEQL + m0 + tid];

    constexpr int MMS = 2, MNS = 4;
    float acc[MMS][MNS][4];
    #pragma unroll
    for (int i = 0; i < MMS; i++)
        #pragma unroll
        for (int j = 0; j < MNS; j++)
            #pragma unroll
            for (int r = 0; r < 4; r++) acc[i][j][r] = 0.f;

    auto load_stage = [&](int st, int k0) {
        uint32_t abase = (uint32_t)__cvta_generic_to_shared(&As[st][0]);
        #pragma unroll
        for (int f = tid; f < BM * BK / 4; f += 256) {
            int row = f >> 3;            // BK/4 == 8
            int kg  = (f & 7) << 2;
            cp_async16(abase + (uint32_t)(row * ASTR + kg) * 4,
                       A + (size_t)(m0 + row) * SEQL + k0 + kg);
        }
        uint32_t bbase = (uint32_t)__cvta_generic_to_shared(&Bs[st][0]);
        #pragma unroll
        for (int f = tid; f < BK * BN / 4; f += 256) {
            int kk = f >> 4;             // BN/4 == 16
            int ng = (f & 15) << 2;
            cp_async16(bbase + (uint32_t)(kk * BSTR + ng) * 4,
                       B + (size_t)(k0 + kk) * DK + ng);
        }
        cp_commit();
    };

    // exp + normalize; gmem gets exact fp32 w, smem gets tf32-rounded w
    auto transform_stage = [&](int st, int k0) {
        float* Asm = As[st];
        #pragma unroll
        for (int f = tid; f < BM * BK / 4; f += 256) {
            int row = f >> 3;
            int kg  = (f & 7) << 2;
            float* p = &Asm[row * ASTR + kg];
            float inv = inv_s[row];
            float w0 = __expf(p[0]) * inv;
            float w1 = __expf(p[1]) * inv;
            float w2 = __expf(p[2]) * inv;
            float w3 = __expf(p[3]) * inv;
            *reinterpret_cast<float4*>(
                &weights[(size_t)z * SEQL * SEQL + (size_t)(m0 + row) * SEQL + k0 + kg]) =
                make_float4(w0, w1, w2, w3);
            p[0] = tf32f(w0); p[1] = tf32f(w1); p[2] = tf32f(w2); p[3] = tf32f(w3);
        }
    };

    auto compute_stage = [&](int st) {
        const float* __restrict__ Bsm = Bs[st];
        const uint32_t abase = (uint32_t)__cvta_generic_to_shared(&As[st][0]);
        #pragma unroll
        for (int kk = 0; kk < BK; kk += 8) {
            const int kb = kk + (lane & 3);
            uint32_t af[MMS][4];
            #pragma unroll
            for (int mm = 0; mm < MMS; mm++)
                ldsm_x4(af[mm],
                        abase + (uint32_t)((wm + mm * 16 + arow) * ASTR + kk + acol) * 4);
            uint32_t bf[MNS][2];
            #pragma unroll
            for (int nn = 0; nn < MNS; nn++) {
                int c = wn + nn * 8 + (lane >> 2);
                bf[nn][0] = __float_as_uint(Bsm[kb * BSTR + c]);      // v pre-rounded
                bf[nn][1] = __float_as_uint(Bsm[(kb + 4) * BSTR + c]);
            }
            #pragma unroll
            for (int mm = 0; mm < MMS; mm++)
                #pragma unroll
                for (int nn = 0; nn < MNS; nn++)
                    mma_tf32(acc[mm][nn], af[mm], bf[nn]);
        }
    };

    // 3-stage pipeline
    int stage = 0;
    load_stage(0, 0);
    load_stage(1, BK);
    cp_wait1();
    __syncthreads();           // stage0 data + inv_s ready
    for (int k0 = 2 * BK; k0 < SEQL; k0 += BK) {
        int s2 = stage + 2; if (s2 >= 3) s2 -= 3;
        load_stage(s2, k0);                 // prefetch 2 ahead
        transform_stage(stage, k0 - 2 * BK);
        __syncthreads();                    // transformed smem visible
        compute_stage(stage);
        cp_wait1();                         // next stage's group complete
        __syncthreads();
        stage = (stage + 1 == 3) ? 0 : stage + 1;
    }
    transform_stage(stage, SEQL - 2 * BK);
    __syncthreads();
    compute_stage(stage);
    cp_wait0();
    __syncthreads();
    stage = (stage + 1 == 3) ? 0 : stage + 1;
    transform_stage(stage, SEQL - BK);
    __syncthreads();
    compute_stage(stage);

    // epilogue: ctx [b, s, (h d)], tf32-rounded for the out-GEMM
    const int b = z >> 4, h = z & (NH - 1);
    #pragma unroll
    for (int mm = 0; mm < MMS; mm++) {
        #pragma unroll
        for (int nn = 0; nn < MNS; nn++) {
            #pragma unroll
            for (int half = 0; half < 2; half++) {
                int row = m0 + wm + mm * 16 + (lane >> 2) + half * 8;
                int col = wn + nn * 8 + ((lane & 3) << 1);
                *reinterpret_cast<float2*>(
                    &ctx[(size_t)(b * SEQL + row) * DMODEL + h * DK + col]) =
                    make_float2(tf32f(acc[mm][nn][half * 2 + 0]),
                                tf32f(acc[mm][nn][half * 2 + 1]));
            }
        }
    }
}

extern "C" void kernel_launch(void* const* d_in, const int* in_sizes, int n_in,
                              void* d_out, int out_size)
{
    const float* Q   = (const float*)d_in[0];
    const float* K   = (const float*)d_in[1];
    const float* V   = (const float*)d_in[2];
    const float* WQw = (const float*)d_in[3];
    const float* WQb = (const float*)d_in[4];
    const float* WKw = (const float*)d_in[5];
    const float* WKb = (const float*)d_in[6];
    const float* WVw = (const float*)d_in[7];
    const float* WVb = (const float*)d_in[8];
    const float* Wow = (const float*)d_in[9];
    const float* Wob = (const float*)d_in[10];

    float* out     = (float*)d_out;                              // [8,1024,1024]
    float* weights = out + (size_t)BSZ * SEQL * DMODEL;          // [8,16,1024,1024]
    float* scores  = weights + (size_t)BSZ * NH * SEQL * SEQL;   // [8,16,1024,1024]

    float *qp, *kp, *vp, *cp, *rs;
    float *rq, *rk, *rv, *rwq, *rwk, *rwv, *rwo;
    cudaGetSymbolAddress((void**)&qp, g_q);
    cudaGetSymbolAddress((void**)&kp, g_k);
    cudaGetSymbolAddress((void**)&vp, g_v);
    cudaGetSymbolAddress((void**)&cp, g_ctx);
    cudaGetSymbolAddress((void**)&rs, g_rowsum);
    cudaGetSymbolAddress((void**)&rq, g_rq);
    cudaGetSymbolAddress((void**)&rk, g_rk);
    cudaGetSymbolAddress((void**)&rv, g_rv);
    cudaGetSymbolAddress((void**)&rwq, g_rwq);
    cudaGetSymbolAddress((void**)&rwk, g_rwk);
    cudaGetSymbolAddress((void**)&rwv, g_rwv);
    cudaGetSymbolAddress((void**)&rwo, g_rwo);

    const int M = BSZ * SEQL;  // 8192

    cudaMemsetAsync(rs, 0, (size_t)BSZ * NH * SEQL * sizeof(float));

    // Prep: tf32-round inputs and weights once (removes all inner-loop cvts)
    const int nx4 = (BSZ * SEQL * DMODEL) / 4;     // 2M float4
    const int nw4 = (DMODEL * DMODEL) / 4;         // 256K float4
    round_copy<<<nx4 / 256, 256>>>((const float4*)Q,   (float4*)rq,  nx4);
    round_copy<<<nx4 / 256, 256>>>((const float4*)K,   (float4*)rk,  nx4);
    round_copy<<<nx4 / 256, 256>>>((const float4*)V,   (float4*)rv,  nx4);
    round_copy<<<nw4 / 256, 256>>>((const float4*)WQw, (float4*)rwq, nw4);
    round_copy<<<nw4 / 256, 256>>>((const float4*)WKw, (float4*)rwk, nw4);
    round_copy<<<nw4 / 256, 256>>>((const float4*)WVw, (float4*)rwv, nw4);
    round_copy<<<nw4 / 256, 256>>>((const float4*)Wow, (float4*)rwo, nw4);

    // QKV projections -> [b,h,s,d]; q carries ATT_SCALE; outputs tf32-rounded
    gemm_big<MODE_PROJ, true><<<dim3(DMODEL/128, M/128), 128>>>(rq, rwq, WQb, qp, M, DMODEL, DMODEL, ATT_SCALE);
    gemm_big<MODE_PROJ, true><<<dim3(DMODEL/128, M/128), 128>>>(rk, rwk, WKb, kp, M, DMODEL, DMODEL, 1.0f);
    gemm_big<MODE_PROJ, true><<<dim3(DMODEL/128, M/128), 128>>>(rv, rwv, WVb, vp, M, DMODEL, DMODEL, 1.0f);

    // attn_scores = q_scaled @ k^T ; accumulate per-row exp-sums
    scores_kernel<<<dim3(SEQL/128, SEQL/128, BSZ*NH), 256>>>(qp, kp, scores, rs);

    // attn_weights = exp(scores)/rowsum (written inside), ctx = weights @ v
    pv_fused<<<dim3(1, SEQL/128, BSZ*NH), 256>>>(scores, vp, rs, weights, cp);

    // output = ctx @ Wo + b  (both operands pre-rounded)
    gemm_big<MODE_OUT, false><<<dim3(DMODEL/128, M/128), 128>>>(cp, rwo, Wob, out, M, DMODEL, DMODEL, 1.0f);
}

// round 16
// speedup vs baseline: 1.0392x; 1.0117x over previous
#include <cuda_runtime.h>
#include <cstdint>
#include <cstddef>

#define BSZ 8
#define SEQL 1024
#define DMODEL 1024
#define NH 16
#define DK 64
#define ATT_SCALE 0.125f   // 64^-0.5  (power of two -> exact prescale of q)

// Static scratch (allocation-free rule: __device__ globals)
__device__ float g_q[(size_t)BSZ*NH*SEQL*DK];    // [b,h,s,d] tf32-rounded, x0.125
__device__ float g_k[(size_t)BSZ*NH*SEQL*DK];    // tf32-rounded
__device__ float g_v[(size_t)BSZ*NH*SEQL*DK];    // tf32-rounded
__device__ float g_ctx[(size_t)BSZ*SEQL*DMODEL]; // [b,s,(h d)] tf32-rounded
__device__ float g_rowsum[(size_t)BSZ*NH*SEQL];  // sum of exp(scores) per row
// tf32-pre-rounded inputs; weights stored TRANSPOSED [N][K] for B-side LDSM
__device__ float g_rq[(size_t)BSZ*SEQL*DMODEL];
__device__ float g_rk[(size_t)BSZ*SEQL*DMODEL];
__device__ float g_rv[(size_t)BSZ*SEQL*DMODEL];
__device__ float g_rwq[(size_t)DMODEL*DMODEL];   // WQ^T, tf32-rounded
__device__ float g_rwk[(size_t)DMODEL*DMODEL];   // WK^T
__device__ float g_rwv[(size_t)DMODEL*DMODEL];   // WV^T
__device__ float g_rwo[(size_t)DMODEL*DMODEL];   // Wo^T

enum { MODE_PROJ = 0, MODE_OUT = 3 };

__device__ __forceinline__ uint32_t tf32u(float x) {
    uint32_t u;
    asm("cvt.rna.tf32.f32 %0, %1;" : "=r"(u) : "f"(x));
    return u;
}
__device__ __forceinline__ float tf32f(float x) { return __uint_as_float(tf32u(x)); }

__device__ __forceinline__ void cp_async16(uint32_t smem_addr, const void* gptr) {
    asm volatile("cp.async.cg.shared.global [%0], [%1], 16;\n"
                 :: "r"(smem_addr), "l"(gptr));
}
__device__ __forceinline__ void cp_commit() {
    asm volatile("cp.async.commit_group;\n");
}
__device__ __forceinline__ void cp_wait0() {
    asm volatile("cp.async.wait_group 0;\n");
}
__device__ __forceinline__ void cp_wait1() {
    asm volatile("cp.async.wait_group 1;\n");
}

__device__ __forceinline__ void mma_tf32(float c[4], const uint32_t a[4], const uint32_t b[2]) {
    asm volatile(
        "mma.sync.aligned.m16n8k8.row.col.f32.tf32.tf32.f32 "
        "{%0,%1,%2,%3}, {%4,%5,%6,%7}, {%8,%9}, {%0,%1,%2,%3};"
        : "+f"(c[0]), "+f"(c[1]), "+f"(c[2]), "+f"(c[3])
        : "r"(a[0]), "r"(a[1]), "r"(a[2]), "r"(a[3]), "r"(b[0]), "r"(b[1]));
}

// ldmatrix x4: four 8x8 b16 tiles (= four 8x4 tf32 tiles), type-agnostic.
__device__ __forceinline__ void ldsm_x4(uint32_t a[4], uint32_t addr) {
    asm volatile("ldmatrix.sync.aligned.m8n8.x4.shared.b16 {%0,%1,%2,%3}, [%4];"
                 : "=r"(a[0]), "=r"(a[1]), "=r"(a[2]), "=r"(a[3]) : "r"(addr));
}
// A-fragment LDSM lane mapping: arow=(lane&7)+((lane>>3)&1)*8 ; acol=((lane>>4)<<2)
// B-fragment (n-major) mapping:  brow=(lane&7)+((lane>>4)<<3) ; bcol=((lane>>3)&1)*4

// ============================================================================
// Elementwise tf32-rounding copy (prep for inputs), float4-vectorized.
// ============================================================================
__global__ void __launch_bounds__(256) round_copy(
    const float4* __restrict__ in, float4* __restrict__ out, int n4)
{
    int i = blockIdx.x * 256 + threadIdx.x;
    if (i < n4) {
        float4 v = in[i];
        v.x = tf32f(v.x); v.y = tf32f(v.y); v.z = tf32f(v.z); v.w = tf32f(v.w);
        out[i] = v;
    }
}

// ============================================================================
// Tiled transpose + tf32 rounding: out[N][K] = round(in[K][N]).
// block (32,8), grid (N/32, K/32).
// ============================================================================
__global__ void __launch_bounds__(256) round_transpose(
    const float* __restrict__ in, float* __restrict__ out, int Kdim, int Ndim)
{
    __shared__ float t[32][33];
    const int k0 = blockIdx.y * 32, n0 = blockIdx.x * 32;
    const int x = threadIdx.x, y = threadIdx.y;
    #pragma unroll
    for (int i = y; i < 32; i += 8)
        t[i][x] = in[(size_t)(k0 + i) * Ndim + n0 + x];
    __syncthreads();
    #pragma unroll
    for (int i = y; i < 32; i += 8)
        out[(size_t)(n0 + i) * Kdim + k0 + x] = tf32f(t[x][i]);
}

// ============================================================================
// Big-K GEMM (K=1024): 256 threads, 8 warps, 64x32 warp tile, BK=32,
// 2-stage cp.async, BOTH operands via ldmatrix (A k-major, B = W^T n-major).
// Operands PRE-ROUNDED tf32. C = (A@B + bias) * out_scale.
//  MODE_PROJ: scatter C into [b,h,s,d] scratch; MODE_OUT: row-major C.
// ============================================================================
template <int MODE, bool ROUND_C>
__global__ void __launch_bounds__(256, 2) gemm_big2(
    const float* __restrict__ A, const float* __restrict__ BT,
    const float* __restrict__ bias, float* __restrict__ C,
    int M, int N, int K, float out_scale)
{
    constexpr int BM = 128, BN = 128, BK = 32;
    constexpr int ASTR = BK + 4;   // 36 floats = 144B rows (16B aligned)
    constexpr int BSTR = BK + 4;   // n-major rows of W^T, same stride
    __shared__ float As[2][BM * ASTR];
    __shared__ float Bs[2][BN * BSTR];

    const int tid  = threadIdx.x;
    const int lane = tid & 31;
    const int warp = tid >> 5;
    const int wm = (warp >> 2) * 64;        // 2 warps in M
    const int wn = (warp & 3) * 32;         // 4 warps in N
    const int m0 = blockIdx.y * BM;
    const int n0 = blockIdx.x * BN;

    const int arow = (lane & 7) + ((lane >> 3) & 1) * 8;
    const int acol = ((lane >> 4) << 2);
    const int brow = (lane & 7) + ((lane >> 4) << 3);
    const int bcol = ((lane >> 3) & 1) * 4;

    constexpr int MMS = 4, MNS = 4;
    float acc[MMS][MNS][4];
    #pragma unroll
    for (int i = 0; i < MMS; i++)
        #pragma unroll
        for (int j = 0; j < MNS; j++)
            #pragma unroll
            for (int r = 0; r < 4; r++) acc[i][j][r] = 0.f;

    auto load_stage = [&](int st, int k0) {
        uint32_t abase = (uint32_t)__cvta_generic_to_shared(&As[st][0]);
        #pragma unroll
        for (int f = tid; f < BM * BK / 4; f += 256) {
            int row = f >> 3;            // BK/4 == 8
            int kg  = (f & 7) << 2;
            cp_async16(abase + (uint32_t)(row * ASTR + kg) * 4,
                       A + (size_t)(m0 + row) * K + k0 + kg);
        }
        uint32_t bbase = (uint32_t)__cvta_generic_to_shared(&Bs[st][0]);
        #pragma unroll
        for (int f = tid; f < BN * BK / 4; f += 256) {
            int col = f >> 3;            // n index
            int kg  = (f & 7) << 2;
            cp_async16(bbase + (uint32_t)(col * BSTR + kg) * 4,
                       BT + (size_t)(n0 + col) * K + k0 + kg);
        }
        cp_commit();
    };

    auto compute_stage = [&](int st) {
        const uint32_t abase = (uint32_t)__cvta_generic_to_shared(&As[st][0]);
        const uint32_t bbase = (uint32_t)__cvta_generic_to_shared(&Bs[st][0]);
        #pragma unroll
        for (int kk = 0; kk < BK; kk += 8) {
            uint32_t af[MMS][4];
            #pragma unroll
            for (int mm = 0; mm < MMS; mm++)
                ldsm_x4(af[mm],
                        abase + (uint32_t)((wm + mm * 16 + arow) * ASTR + kk + acol) * 4);
            uint32_t bf[MNS][2];
            #pragma unroll
            for (int np = 0; np < MNS / 2; np++) {
                uint32_t t[4];
                ldsm_x4(t, bbase + (uint32_t)((wn + np * 16 + brow) * BSTR + kk + bcol) * 4);
                bf[np * 2 + 0][0] = t[0];
                bf[np * 2 + 0][1] = t[1];
                bf[np * 2 + 1][0] = t[2];
                bf[np * 2 + 1][1] = t[3];
            }
            #pragma unroll
            for (int mm = 0; mm < MMS; mm++)
                #pragma unroll
                for (int nn = 0; nn < MNS; nn++)
                    mma_tf32(acc[mm][nn], af[mm], bf[nn]);
        }
    };

    int stage = 0;
    load_stage(0, 0);
    cp_wait0();
    __syncthreads();
    for (int k0 = BK; k0 < K; k0 += BK) {
        load_stage(stage ^ 1, k0);
        compute_stage(stage);
        cp_wait0();
        __syncthreads();
        stage ^= 1;
    }
    compute_stage(stage);

    #pragma unroll
    for (int mm = 0; mm < MMS; mm++) {
        #pragma unroll
        for (int nn = 0; nn < MNS; nn++) {
            #pragma unroll
            for (int half = 0; half < 2; half++) {
                int row = m0 + wm + mm * 16 + (lane >> 2) + half * 8;
                int col = n0 + wn + nn * 8 + ((lane & 3) << 1);
                float v0 = (acc[mm][nn][half * 2 + 0] + bias[col])     * out_scale;
                float v1 = (acc[mm][nn][half * 2 + 1] + bias[col + 1]) * out_scale;
                if (ROUND_C) { v0 = tf32f(v0); v1 = tf32f(v1); }
                if (MODE == MODE_PROJ) {
                    int b = row >> 10, s = row & (SEQL - 1);
                    int h = col >> 6,  d = col & (DK - 1);
                    *reinterpret_cast<float2*>(
                        &C[((size_t)(b * NH + h) * SEQL + s) * DK + d]) =
                        make_float2(v0, v1);
                } else {
                    *reinterpret_cast<float2*>(&C[(size_t)row * DMODEL + col]) =
                        make_float2(v0, v1);
                }
            }
        }
    }
}

// ============================================================================
// Scores: per z=(b,h), scores = q_scaled @ k^T (q carries the 1/8 scale).
// Both operands pre-rounded tf32, LDSM on A and B (validated R13/R14).
// Epilogue stores scores + exp-rowsums (atomics).
// ============================================================================
__global__ void __launch_bounds__(256, 2) scores_kernel(
    const float* __restrict__ qroot, const float* __restrict__ kroot,
    float* __restrict__ scores, float* __restrict__ rowsum)
{
    constexpr int BM = 128, BN = 128, STR = DK + 4;  // 68 floats = 272B (16B aligned)
    const int z = blockIdx.z;
    const float* A = qroot + (size_t)z * SEQL * DK;
    const float* B = kroot + (size_t)z * SEQL * DK;

    __shared__ float As[BM * STR];
    __shared__ float Bs[BN * STR];

    const int tid  = threadIdx.x;
    const int lane = tid & 31;
    const int warp = tid >> 5;
    const int wm = (warp >> 1) * 32;
    const int wn = (warp & 1) * 64;
    const int m0 = blockIdx.y * BM;
    const int n0 = blockIdx.x * BN;

    const int arow = (lane & 7) + ((lane >> 3) & 1) * 8;
    const int acol = ((lane >> 4) << 2);
    const int brow = (lane & 7) + ((lane >> 4) << 3);
    const int bcol = ((lane >> 3) & 1) * 4;

    {
        uint32_t abase = (uint32_t)__cvta_generic_to_shared(&As[0]);
        uint32_t bbase = (uint32_t)__cvta_generic_to_shared(&Bs[0]);
        #pragma unroll
        for (int f = tid; f < BM * DK / 4; f += 256) {
            int row = f >> 4;            // DK/4 == 16
            int kg  = (f & 15) << 2;
            cp_async16(abase + (uint32_t)(row * STR + kg) * 4,
                       A + (size_t)(m0 + row) * DK + kg);
            cp_async16(bbase + (uint32_t)(row * STR + kg) * 4,
                       B + (size_t)(n0 + row) * DK + kg);
        }
        cp_commit();
        cp_wait0();
        __syncthreads();
    }

    constexpr int MMS = 2, MNS = 8;
    float acc[MMS][MNS][4];
    #pragma unroll
    for (int i = 0; i < MMS; i++)
        #pragma unroll
        for (int j = 0; j < MNS; j++)
            #pragma unroll
            for (int r = 0; r < 4; r++) acc[i][j][r] = 0.f;

    {
        const uint32_t abase = (uint32_t)__cvta_generic_to_shared(&As[0]);
        const uint32_t bbase = (uint32_t)__cvta_generic_to_shared(&Bs[0]);
        uint32_t af[2][MMS][4];
        uint32_t bf[2][MNS][2];
        auto load_frags = [&](int buf, int kk) {
            #pragma unroll
            for (int mm = 0; mm < MMS; mm++)
                ldsm_x4(af[buf][mm],
                        abase + (uint32_t)((wm + mm * 16 + arow) * STR + kk + acol) * 4);
            #pragma unroll
            for (int np = 0; np < MNS / 2; np++) {
                uint32_t t[4];
                ldsm_x4(t, bbase + (uint32_t)((wn + np * 16 + brow) * STR + kk + bcol) * 4);
                bf[buf][np * 2 + 0][0] = t[0];
                bf[buf][np * 2 + 0][1] = t[1];
                bf[buf][np * 2 + 1][0] = t[2];
                bf[buf][np * 2 + 1][1] = t[3];
            }
        };
        load_frags(0, 0);
        #pragma unroll
        for (int kk = 0; kk < DK; kk += 8) {
            int cur = (kk >> 3) & 1;
            if (kk + 8 < DK) load_frags(cur ^ 1, kk + 8);
            #pragma unroll
            for (int mm = 0; mm < MMS; mm++)
                #pragma unroll
                for (int nn = 0; nn < MNS; nn++)
                    mma_tf32(acc[mm][nn], af[cur][mm], bf[cur][nn]);
        }
    }

    float esum[MMS][2];
    #pragma unroll
    for (int mm = 0; mm < MMS; mm++) { esum[mm][0] = 0.f; esum[mm][1] = 0.f; }

    #pragma unroll
    for (int mm = 0; mm < MMS; mm++) {
        #pragma unroll
        for (int nn = 0; nn < MNS; nn++) {
            #pragma unroll
            for (int half = 0; half < 2; half++) {
                int row = m0 + wm + mm * 16 + (lane >> 2) + half * 8;
                int col = n0 + wn + nn * 8 + ((lane & 3) << 1);
                float v0 = acc[mm][nn][half * 2 + 0];
                float v1 = acc[mm][nn][half * 2 + 1];
                *reinterpret_cast<float2*>(
                    &scores[(size_t)z * SEQL * SEQL + (size_t)row * SEQL + col]) =
                    make_float2(v0, v1);
                esum[mm][half] += __expf(v0) + __expf(v1);
            }
        }
    }
    #pragma unroll
    for (int mm = 0; mm < MMS; mm++) {
        #pragma unroll
        for (int half = 0; half < 2; half++) {
            float s = esum[mm][half];
            s += __shfl_xor_sync(~0u, s, 1);
            s += __shfl_xor_sync(~0u, s, 2);
            if ((lane & 3) == 0) {
                int row = m0 + wm + mm * 16 + (lane >> 2) + half * 8;
                atomicAdd(&rowsum[(size_t)z * SEQL + row], s);
            }
        }
    }
}

// ============================================================================
// Fused softmax + PV: per z=(b,h). 3-stage cp.async pipeline (wait_group 1).
// transform computes w = exp(s)*inv_rowsum, writes exact fp32 w to gmem
// weights, stores tf32-rounded w into smem -> A-side LDSM, no cvt in MMA loop.
// ctx = w @ v. BK=32.
// ============================================================================
__global__ void __launch_bounds__(256, 2) pv_fused(
    const float* __restrict__ scores, const float* __restrict__ vroot,
    const float* __restrict__ rowsum,
    float* __restrict__ weights, float* __restrict__ ctx)
{
    constexpr int BM = 128, BN = 64, BK = 32;
    constexpr int ASTR = BK + 4;   // 36 floats = 144B (16B aligned)
    constexpr int BSTR = BN + 8;   // 72
    const int z = blockIdx.z;
    const float* A = scores + (size_t)z * SEQL * SEQL;   // [1024,1024]
    const float* B = vroot  + (size_t)z * SEQL * DK;     // [1024,64]

    __shared__ float As[3][BM * ASTR];
    __shared__ float Bs[3][BK * BSTR];
    __shared__ float inv_s[BM];

    const int tid  = threadIdx.x;
    const int lane = tid & 31;
    const int warp = tid >> 5;
    const int wm = (warp >> 1) * 32;
    const int wn = (warp & 1) * 32;
    const int m0 = blockIdx.y * BM;

    const int arow = (lane & 7) + ((lane >> 3) & 1) * 8;
    const int acol = ((lane >> 4) << 2);

    if (tid < BM)
        inv_s[tid] = 1.0f / rowsum[(size_t)z * SEQL + m0 + tid];

    constexpr int MMS = 2, MNS = 4;
    float acc[MMS][MNS][4];
    #pragma unroll
    for (int i = 0; i < MMS; i++)
        #pragma unroll
        for (int j = 0; j < MNS; j++)
            #pragma unroll
            for (int r = 0; r < 4; r++) acc[i][j][r] = 0.f;

    auto load_stage = [&](int st, int k0) {
        uint32_t abase = (uint32_t)__cvta_generic_to_shared(&As[st][0]);
        #pragma unroll
        for (int f = tid; f < BM * BK / 4; f += 256) {
            int row = f >> 3;            // BK/4 == 8
            int kg  = (f & 7) << 2;
            cp_async16(abase + (uint32_t)(row * ASTR + kg) * 4,
                       A + (size_t)(m0 + row) * SEQL + k0 + kg);
        }
        uint32_t bbase = (uint32_t)__cvta_generic_to_shared(&Bs[st][0]);
        #pragma unroll
        for (int f = tid; f < BK * BN / 4; f += 256) {
            int kk = f >> 4;             // BN/4 == 16
            int ng = (f & 15) << 2;
            cp_async16(bbase + (uint32_t)(kk * BSTR + ng) * 4,
                       B + (size_t)(k0 + kk) * DK + ng);
        }
        cp_commit();
    };

    // exp + normalize; gmem gets exact fp32 w, smem gets tf32-rounded w
    auto transform_stage = [&](int st, int k0) {
        float* Asm = As[st];
        #pragma unroll
        for (int f = tid; f < BM * BK / 4; f += 256) {
            int row = f >> 3;
            int kg  = (f & 7) << 2;
            float* p = &Asm[row * ASTR + kg];
            float inv = inv_s[row];
            float w0 = __expf(p[0]) * inv;
            float w1 = __expf(p[1]) * inv;
            float w2 = __expf(p[2]) * inv;
            float w3 = __expf(p[3]) * inv;
            *reinterpret_cast<float4*>(
                &weights[(size_t)z * SEQL * SEQL + (size_t)(m0 + row) * SEQL + k0 + kg]) =
                make_float4(w0, w1, w2, w3);
            p[0] = tf32f(w0); p[1] = tf32f(w1); p[2] = tf32f(w2); p[3] = tf32f(w3);
        }
    };

    auto compute_stage = [&](int st) {
        const float* __restrict__ Bsm = Bs[st];
        const uint32_t abase = (uint32_t)__cvta_generic_to_shared(&As[st][0]);
        #pragma unroll
        for (int kk = 0; kk < BK; kk += 8) {
            const int kb = kk + (lane & 3);
            uint32_t af[MMS][4];
            #pragma unroll
            for (int mm = 0; mm < MMS; mm++)
                ldsm_x4(af[mm],
                        abase + (uint32_t)((wm + mm * 16 + arow) * ASTR + kk + acol) * 4);
            uint32_t bf[MNS][2];
            #pragma unroll
            for (int nn = 0; nn < MNS; nn++) {
                int c = wn + nn * 8 + (lane >> 2);
                bf[nn][0] = __float_as_uint(Bsm[kb * BSTR + c]);      // v pre-rounded
                bf[nn][1] = __float_as_uint(Bsm[(kb + 4) * BSTR + c]);
            }
            #pragma unroll
            for (int mm = 0; mm < MMS; mm++)
                #pragma unroll
                for (int nn = 0; nn < MNS; nn++)
                    mma_tf32(acc[mm][nn], af[mm], bf[nn]);
        }
    };

    // 3-stage pipeline
    int stage = 0;
    load_stage(0, 0);
    load_stage(1, BK);
    cp_wait1();
    __syncthreads();           // stage0 data + inv_s ready
    for (int k0 = 2 * BK; k0 < SEQL; k0 += BK) {
        int s2 = stage + 2; if (s2 >= 3) s2 -= 3;
        load_stage(s2, k0);                 // prefetch 2 ahead
        transform_stage(stage, k0 - 2 * BK);
        __syncthreads();                    // transformed smem visible
        compute_stage(stage);
        cp_wait1();                         // next stage's group complete
        __syncthreads();
        stage = (stage + 1 == 3) ? 0 : stage + 1;
    }
    transform_stage(stage, SEQL - 2 * BK);
    __syncthreads();
    compute_stage(stage);
    cp_wait0();
    __syncthreads();
    stage = (stage + 1 == 3) ? 0 : stage + 1;
    transform_stage(stage, SEQL - BK);
    __syncthreads();
    compute_stage(stage);

    // epilogue: ctx [b, s, (h d)], tf32-rounded for the out-GEMM
    const int b = z >> 4, h = z & (NH - 1);
    #pragma unroll
    for (int mm = 0; mm < MMS; mm++) {
        #pragma unroll
        for (int nn = 0; nn < MNS; nn++) {
            #pragma unroll
            for (int half = 0; half < 2; half++) {
                int row = m0 + wm + mm * 16 + (lane >> 2) + half * 8;
                int col = wn + nn * 8 + ((lane & 3) << 1);
                *reinterpret_cast<float2*>(
                    &ctx[(size_t)(b * SEQL + row) * DMODEL + h * DK + col]) =
                    make_float2(tf32f(acc[mm][nn][half * 2 + 0]),
                                tf32f(acc[mm][nn][half * 2 + 1]));
            }
        }
    }
}

extern "C" void kernel_launch(void* const* d_in, const int* in_sizes, int n_in,
                              void* d_out, int out_size)
{
    const float* Q   = (const float*)d_in[0];
    const float* K   = (const float*)d_in[1];
    const float* V   = (const float*)d_in[2];
    const float* WQw = (const float*)d_in[3];
    const float* WQb = (const float*)d_in[4];
    const float* WKw = (const float*)d_in[5];
    const float* WKb = (const float*)d_in[6];
    const float* WVw = (const float*)d_in[7];
    const float* WVb = (const float*)d_in[8];
    const float* Wow = (const float*)d_in[9];
    const float* Wob = (const float*)d_in[10];

    float* out     = (float*)d_out;                              // [8,1024,1024]
    float* weights = out + (size_t)BSZ * SEQL * DMODEL;          // [8,16,1024,1024]
    float* scores  = weights + (size_t)BSZ * NH * SEQL * SEQL;   // [8,16,1024,1024]

    float *qp, *kp, *vp, *cp, *rs;
    float *rq, *rk, *rv, *rwq, *rwk, *rwv, *rwo;
    cudaGetSymbolAddress((void**)&qp, g_q);
    cudaGetSymbolAddress((void**)&kp, g_k);
    cudaGetSymbolAddress((void**)&vp, g_v);
    cudaGetSymbolAddress((void**)&cp, g_ctx);
    cudaGetSymbolAddress((void**)&rs, g_rowsum);
    cudaGetSymbolAddress((void**)&rq, g_rq);
    cudaGetSymbolAddress((void**)&rk, g_rk);
    cudaGetSymbolAddress((void**)&rv, g_rv);
    cudaGetSymbolAddress((void**)&rwq, g_rwq);
    cudaGetSymbolAddress((void**)&rwk, g_rwk);
    cudaGetSymbolAddress((void**)&rwv, g_rwv);
    cudaGetSymbolAddress((void**)&rwo, g_rwo);

    const int M = BSZ * SEQL;  // 8192

    cudaMemsetAsync(rs, 0, (size_t)BSZ * NH * SEQL * sizeof(float));

    // Prep: tf32-round inputs; round+TRANSPOSE weights (for B-side LDSM)
    const int nx4 = (BSZ * SEQL * DMODEL) / 4;     // 2M float4
    round_copy<<<nx4 / 256, 256>>>((const float4*)Q, (float4*)rq, nx4);
    round_copy<<<nx4 / 256, 256>>>((const float4*)K, (float4*)rk, nx4);
    round_copy<<<nx4 / 256, 256>>>((const float4*)V, (float4*)rv, nx4);
    {
        dim3 tg(DMODEL / 32, DMODEL / 32);
        dim3 tb(32, 8);
        round_transpose<<<tg, tb>>>(WQw, rwq, DMODEL, DMODEL);
        round_transpose<<<tg, tb>>>(WKw, rwk, DMODEL, DMODEL);
        round_transpose<<<tg, tb>>>(WVw, rwv, DMODEL, DMODEL);
        round_transpose<<<tg, tb>>>(Wow, rwo, DMODEL, DMODEL);
    }

    // QKV projections -> [b,h,s,d]; q carries ATT_SCALE; outputs tf32-rounded
    gemm_big2<MODE_PROJ, true><<<dim3(DMODEL/128, M/128), 256>>>(rq, rwq, WQb, qp, M, DMODEL, DMODEL, ATT_SCALE);
    gemm_big2<MODE_PROJ, true><<<dim3(DMODEL/128, M/128), 256>>>(rk, rwk, WKb, kp, M, DMODEL, DMODEL, 1.0f);
    gemm_big2<MODE_PROJ, true><<<dim3(DMODEL/128, M/128), 256>>>(rv, rwv, WVb, vp, M, DMODEL, DMODEL, 1.0f);

    // attn_scores = q_scaled @ k^T ; accumulate per-row exp-sums
    scores_kernel<<<dim3(SEQL/128, SEQL/128, BSZ*NH), 256>>>(qp, kp, scores, rs);

    // attn_weights = exp(scores)/rowsum (written inside), ctx = weights @ v
    pv_fused<<<dim3(1, SEQL/128, BSZ*NH), 256>>>(scores, vp, rs, weights, cp);

    // output = ctx @ Wo + b  (both operands pre-rounded; Wo transposed)
    gemm_big2<MODE_OUT, false><<<dim3(DMODEL/128, M/128), 256>>>(cp, rwo, Wob, out, M, DMODEL, DMODEL, 1.0f);
}

// round 17
// speedup vs baseline: 1.0476x; 1.0081x over previous
#include <cuda_runtime.h>
#include <cstdint>
#include <cstddef>

#define BSZ 8
#define SEQL 1024
#define DMODEL 1024
#define NH 16
#define DK 64
#define ATT_SCALE 0.125f   // 64^-0.5  (power of two -> exact prescale of q)

// Static scratch (allocation-free rule: __device__ globals)
__device__ float g_q[(size_t)BSZ*NH*SEQL*DK];    // [b,h,s,d] tf32-rounded, x0.125
__device__ float g_k[(size_t)BSZ*NH*SEQL*DK];    // tf32-rounded
__device__ float g_v[(size_t)BSZ*NH*SEQL*DK];    // tf32-rounded
__device__ float g_ctx[(size_t)BSZ*SEQL*DMODEL]; // [b,s,(h d)] tf32-rounded
// tf32-pre-rounded inputs; weights stored TRANSPOSED [N][K] for B-side LDSM
__device__ float g_rq[(size_t)BSZ*SEQL*DMODEL];
__device__ float g_rk[(size_t)BSZ*SEQL*DMODEL];
__device__ float g_rv[(size_t)BSZ*SEQL*DMODEL];
__device__ float g_rwq[(size_t)DMODEL*DMODEL];   // WQ^T, tf32-rounded
__device__ float g_rwk[(size_t)DMODEL*DMODEL];   // WK^T
__device__ float g_rwv[(size_t)DMODEL*DMODEL];   // WV^T
__device__ float g_rwo[(size_t)DMODEL*DMODEL];   // Wo^T

enum { MODE_PROJ = 0, MODE_OUT = 3 };

__device__ __forceinline__ uint32_t tf32u(float x) {
    uint32_t u;
    asm("cvt.rna.tf32.f32 %0, %1;" : "=r"(u) : "f"(x));
    return u;
}
__device__ __forceinline__ float tf32f(float x) { return __uint_as_float(tf32u(x)); }

__device__ __forceinline__ void cp_async16(uint32_t smem_addr, const void* gptr) {
    asm volatile("cp.async.cg.shared.global [%0], [%1], 16;\n"
                 :: "r"(smem_addr), "l"(gptr));
}
__device__ __forceinline__ void cp_commit() {
    asm volatile("cp.async.commit_group;\n");
}
__device__ __forceinline__ void cp_wait0() {
    asm volatile("cp.async.wait_group 0;\n");
}

__device__ __forceinline__ void mma_tf32(float c[4], const uint32_t a[4], const uint32_t b[2]) {
    asm volatile(
        "mma.sync.aligned.m16n8k8.row.col.f32.tf32.tf32.f32 "
        "{%0,%1,%2,%3}, {%4,%5,%6,%7}, {%8,%9}, {%0,%1,%2,%3};"
        : "+f"(c[0]), "+f"(c[1]), "+f"(c[2]), "+f"(c[3])
        : "r"(a[0]), "r"(a[1]), "r"(a[2]), "r"(a[3]), "r"(b[0]), "r"(b[1]));
}

// ldmatrix x4: four 8x8 b16 tiles (= four 8x4 tf32 tiles), type-agnostic.
__device__ __forceinline__ void ldsm_x4(uint32_t a[4], uint32_t addr) {
    asm volatile("ldmatrix.sync.aligned.m8n8.x4.shared.b16 {%0,%1,%2,%3}, [%4];"
                 : "=r"(a[0]), "=r"(a[1]), "=r"(a[2]), "=r"(a[3]) : "r"(addr));
}
// A-fragment LDSM lane mapping: arow=(lane&7)+((lane>>3)&1)*8 ; acol=((lane>>4)<<2)
// B-fragment (n-major) mapping:  brow=(lane&7)+((lane>>4)<<3) ; bcol=((lane>>3)&1)*4

// ============================================================================
// Elementwise tf32-rounding copy (prep for inputs), float4-vectorized.
// ============================================================================
__global__ void __launch_bounds__(256) round_copy(
    const float4* __restrict__ in, float4* __restrict__ out, int n4)
{
    int i = blockIdx.x * 256 + threadIdx.x;
    if (i < n4) {
        float4 v = in[i];
        v.x = tf32f(v.x); v.y = tf32f(v.y); v.z = tf32f(v.z); v.w = tf32f(v.w);
        out[i] = v;
    }
}

// ============================================================================
// Tiled transpose + tf32 rounding: out[N][K] = round(in[K][N]).
// ============================================================================
__global__ void __launch_bounds__(256) round_transpose(
    const float* __restrict__ in, float* __restrict__ out, int Kdim, int Ndim)
{
    __shared__ float t[32][33];
    const int k0 = blockIdx.y * 32, n0 = blockIdx.x * 32;
    const int x = threadIdx.x, y = threadIdx.y;
    #pragma unroll
    for (int i = y; i < 32; i += 8)
        t[i][x] = in[(size_t)(k0 + i) * Ndim + n0 + x];
    __syncthreads();
    #pragma unroll
    for (int i = y; i < 32; i += 8)
        out[(size_t)(n0 + i) * Kdim + k0 + x] = tf32f(t[x][i]);
}

// ============================================================================
// Big-K GEMM (K=1024): 256 threads, 8 warps, 64x32 warp tile, BK=32,
// 2-stage cp.async, BOTH operands via ldmatrix (validated R16).
// ============================================================================
template <int MODE, bool ROUND_C>
__global__ void __launch_bounds__(256, 2) gemm_big2(
    const float* __restrict__ A, const float* __restrict__ BT,
    const float* __restrict__ bias, float* __restrict__ C,
    int M, int N, int K, float out_scale)
{
    constexpr int BM = 128, BN = 128, BK = 32;
    constexpr int ASTR = BK + 4;   // 36 floats = 144B rows (16B aligned)
    constexpr int BSTR = BK + 4;
    __shared__ float As[2][BM * ASTR];
    __shared__ float Bs[2][BN * BSTR];

    const int tid  = threadIdx.x;
    const int lane = tid & 31;
    const int warp = tid >> 5;
    const int wm = (warp >> 2) * 64;
    const int wn = (warp & 3) * 32;
    const int m0 = blockIdx.y * BM;
    const int n0 = blockIdx.x * BN;

    const int arow = (lane & 7) + ((lane >> 3) & 1) * 8;
    const int acol = ((lane >> 4) << 2);
    const int brow = (lane & 7) + ((lane >> 4) << 3);
    const int bcol = ((lane >> 3) & 1) * 4;

    constexpr int MMS = 4, MNS = 4;
    float acc[MMS][MNS][4];
    #pragma unroll
    for (int i = 0; i < MMS; i++)
        #pragma unroll
        for (int j = 0; j < MNS; j++)
            #pragma unroll
            for (int r = 0; r < 4; r++) acc[i][j][r] = 0.f;

    auto load_stage = [&](int st, int k0) {
        uint32_t abase = (uint32_t)__cvta_generic_to_shared(&As[st][0]);
        #pragma unroll
        for (int f = tid; f < BM * BK / 4; f += 256) {
            int row = f >> 3;
            int kg  = (f & 7) << 2;
            cp_async16(abase + (uint32_t)(row * ASTR + kg) * 4,
                       A + (size_t)(m0 + row) * K + k0 + kg);
        }
        uint32_t bbase = (uint32_t)__cvta_generic_to_shared(&Bs[st][0]);
        #pragma unroll
        for (int f = tid; f < BN * BK / 4; f += 256) {
            int col = f >> 3;
            int kg  = (f & 7) << 2;
            cp_async16(bbase + (uint32_t)(col * BSTR + kg) * 4,
                       BT + (size_t)(n0 + col) * K + k0 + kg);
        }
        cp_commit();
    };

    auto compute_stage = [&](int st) {
        const uint32_t abase = (uint32_t)__cvta_generic_to_shared(&As[st][0]);
        const uint32_t bbase = (uint32_t)__cvta_generic_to_shared(&Bs[st][0]);
        #pragma unroll
        for (int kk = 0; kk < BK; kk += 8) {
            uint32_t af[MMS][4];
            #pragma unroll
            for (int mm = 0; mm < MMS; mm++)
                ldsm_x4(af[mm],
                        abase + (uint32_t)((wm + mm * 16 + arow) * ASTR + kk + acol) * 4);
            uint32_t bf[MNS][2];
            #pragma unroll
            for (int np = 0; np < MNS / 2; np++) {
                uint32_t t[4];
                ldsm_x4(t, bbase + (uint32_t)((wn + np * 16 + brow) * BSTR + kk + bcol) * 4);
                bf[np * 2 + 0][0] = t[0];
                bf[np * 2 + 0][1] = t[1];
                bf[np * 2 + 1][0] = t[2];
                bf[np * 2 + 1][1] = t[3];
            }
            #pragma unroll
            for (int mm = 0; mm < MMS; mm++)
                #pragma unroll
                for (int nn = 0; nn < MNS; nn++)
                    mma_tf32(acc[mm][nn], af[mm], bf[nn]);
        }
    };

    int stage = 0;
    load_stage(0, 0);
    cp_wait0();
    __syncthreads();
    for (int k0 = BK; k0 < K; k0 += BK) {
        load_stage(stage ^ 1, k0);
        compute_stage(stage);
        cp_wait0();
        __syncthreads();
        stage ^= 1;
    }
    compute_stage(stage);

    #pragma unroll
    for (int mm = 0; mm < MMS; mm++) {
        #pragma unroll
        for (int nn = 0; nn < MNS; nn++) {
            #pragma unroll
            for (int half = 0; half < 2; half++) {
                int row = m0 + wm + mm * 16 + (lane >> 2) + half * 8;
                int col = n0 + wn + nn * 8 + ((lane & 3) << 1);
                float v0 = (acc[mm][nn][half * 2 + 0] + bias[col])     * out_scale;
                float v1 = (acc[mm][nn][half * 2 + 1] + bias[col + 1]) * out_scale;
                if (ROUND_C) { v0 = tf32f(v0); v1 = tf32f(v1); }
                if (MODE == MODE_PROJ) {
                    int b = row >> 10, s = row & (SEQL - 1);
                    int h = col >> 6,  d = col & (DK - 1);
                    *reinterpret_cast<float2*>(
                        &C[((size_t)(b * NH + h) * SEQL + s) * DK + d]) =
                        make_float2(v0, v1);
                } else {
                    *reinterpret_cast<float2*>(&C[(size_t)row * DMODEL + col]) =
                        make_float2(v0, v1);
                }
            }
        }
    }
}

// ============================================================================
// Fused attention middle: per CTA = (z, 128-row m-block).
// Phase 1: stream 16 k-tiles (64 rows each), s = q_scaled @ k^T, write scores,
//          accumulate per-row exp-sums in regs -> smem (no global atomics).
// Phase 2: REVERSE tile order; re-read own scores (L2-resident), transform
//          w = exp(s)*inv (fp32 -> gmem weights, tf32 -> smem), ctx += w @ v.
// 256 threads, 8 warps (4x2 of 32x32 tiles). ~103 KB dynamic smem, 2 CTAs/SM.
// ============================================================================
#define BMA 128
#define BNT 64
#define NT  (SEQL / BNT)     // 16
#define FSTR (DK + 4)        // 68 floats = 272B rows (16B aligned)

#define SM_Q   0                                   // [128][68]      34816 B
#define SM_K   34816                               // [2][64][68]    34816 B
#define SM_S   0                                   // [2][128][68]   69632 B (phase2)
#define SM_V   69632                               // [2][64][68]    34816 B
#define SM_RS  104448                              // rsum[128]        512 B
#define SM_INV 104960                              // inv[128]         512 B
#define SM_TOTAL 105472

__global__ void __launch_bounds__(256, 2) attn_fused(
    const float* __restrict__ qroot, const float* __restrict__ kroot,
    const float* __restrict__ vroot,
    float* __restrict__ scores, float* __restrict__ weights,
    float* __restrict__ ctx)
{
    extern __shared__ char smraw[];
    float* qs   = (float*)(smraw + SM_Q);
    float* ks   = (float*)(smraw + SM_K);
    float* ss   = (float*)(smraw + SM_S);
    float* vs   = (float*)(smraw + SM_V);
    float* rsum = (float*)(smraw + SM_RS);
    float* invs = (float*)(smraw + SM_INV);

    const int z  = blockIdx.z;
    const int m0 = blockIdx.y * BMA;
    const float* qp = qroot + (size_t)z * SEQL * DK;
    const float* kp = kroot + (size_t)z * SEQL * DK;
    const float* vp = vroot + (size_t)z * SEQL * DK;
    float* sc = scores  + (size_t)z * SEQL * SEQL;
    float* wg = weights + (size_t)z * SEQL * SEQL;

    const int tid  = threadIdx.x;
    const int lane = tid & 31;
    const int warp = tid >> 5;
    const int wm = (warp >> 1) * 32;     // 4 warps in M
    const int wn = (warp & 1) * 32;      // 2 warps in N
    const int arow = (lane & 7) + ((lane >> 3) & 1) * 8;
    const int acol = ((lane >> 4) << 2);
    const int brow = (lane & 7) + ((lane >> 4) << 3);
    const int bcol = ((lane >> 3) & 1) * 4;

    if (tid < BMA) rsum[tid] = 0.f;

    // ---------- Phase 1: scores + rowsum ----------
    {
        // load q block [128][64] + k tile 0
        uint32_t qbase = (uint32_t)__cvta_generic_to_shared(qs);
        #pragma unroll
        for (int f = tid; f < BMA * DK / 4; f += 256) {
            int row = f >> 4;
            int kg  = (f & 15) << 2;
            cp_async16(qbase + (uint32_t)(row * FSTR + kg) * 4,
                       qp + (size_t)(m0 + row) * DK + kg);
        }
        auto load_k = [&](int st, int t) {
            uint32_t kbase = (uint32_t)__cvta_generic_to_shared(ks + st * BNT * FSTR);
            #pragma unroll
            for (int f = tid; f < BNT * DK / 4; f += 256) {
                int row = f >> 4;
                int kg  = (f & 15) << 2;
                cp_async16(kbase + (uint32_t)(row * FSTR + kg) * 4,
                           kp + (size_t)(t * BNT + row) * DK + kg);
            }
            cp_commit();
        };
        load_k(0, 0);
        cp_wait0();
        __syncthreads();

        float esum[2][2] = {{0.f, 0.f}, {0.f, 0.f}};
        const uint32_t qb = (uint32_t)__cvta_generic_to_shared(qs);
        int st = 0;
        for (int t = 0; t < NT; t++) {
            if (t + 1 < NT) load_k(st ^ 1, t + 1);

            float acc[2][4][4];
            #pragma unroll
            for (int i = 0; i < 2; i++)
                #pragma unroll
                for (int j = 0; j < 4; j++)
                    #pragma unroll
                    for (int r = 0; r < 4; r++) acc[i][j][r] = 0.f;

            const uint32_t kb = (uint32_t)__cvta_generic_to_shared(ks + st * BNT * FSTR);
            #pragma unroll
            for (int kk = 0; kk < DK; kk += 8) {
                uint32_t af[2][4];
                #pragma unroll
                for (int mm = 0; mm < 2; mm++)
                    ldsm_x4(af[mm], qb + (uint32_t)((wm + mm * 16 + arow) * FSTR + kk + acol) * 4);
                uint32_t bf[4][2];
                #pragma unroll
                for (int np = 0; np < 2; np++) {
                    uint32_t tt[4];
                    ldsm_x4(tt, kb + (uint32_t)((wn + np * 16 + brow) * FSTR + kk + bcol) * 4);
                    bf[np * 2 + 0][0] = tt[0];
                    bf[np * 2 + 0][1] = tt[1];
                    bf[np * 2 + 1][0] = tt[2];
                    bf[np * 2 + 1][1] = tt[3];
                }
                #pragma unroll
                for (int mm = 0; mm < 2; mm++)
                    #pragma unroll
                    for (int nn = 0; nn < 4; nn++)
                        mma_tf32(acc[mm][nn], af[mm], bf[nn]);
            }

            // epilogue: write scores + accumulate exp sums
            #pragma unroll
            for (int mm = 0; mm < 2; mm++)
                #pragma unroll
                for (int nn = 0; nn < 4; nn++)
                    #pragma unroll
                    for (int half = 0; half < 2; half++) {
                        int row = m0 + wm + mm * 16 + (lane >> 2) + half * 8;
                        int col = t * BNT + wn + nn * 8 + ((lane & 3) << 1);
                        float v0 = acc[mm][nn][half * 2 + 0];
                        float v1 = acc[mm][nn][half * 2 + 1];
                        *reinterpret_cast<float2*>(&sc[(size_t)row * SEQL + col]) =
                            make_float2(v0, v1);
                        esum[mm][half] += __expf(v0) + __expf(v1);
                    }

            cp_wait0();
            __syncthreads();
            st ^= 1;
        }

        // reduce exp sums: lanes sharing a row (lane&3 group), then smem atomics
        #pragma unroll
        for (int mm = 0; mm < 2; mm++)
            #pragma unroll
            for (int half = 0; half < 2; half++) {
                float s = esum[mm][half];
                s += __shfl_xor_sync(~0u, s, 1);
                s += __shfl_xor_sync(~0u, s, 2);
                if ((lane & 3) == 0) {
                    int rl = wm + mm * 16 + (lane >> 2) + half * 8;
                    atomicAdd(&rsum[rl], s);
                }
            }
        __syncthreads();
        if (tid < BMA) invs[tid] = 1.0f / rsum[tid];
        __syncthreads();   // invs ready; phase-1 smem reads done (alias reuse safe)
    }

    // ---------- Phase 2: weights + ctx = w @ v (reverse tile order) ----------
    {
        auto load_sv = [&](int st, int t) {
            uint32_t sbase = (uint32_t)__cvta_generic_to_shared(ss + st * BMA * FSTR);
            #pragma unroll
            for (int f = tid; f < BMA * BNT / 4; f += 256) {
                int row = f >> 4;
                int kg  = (f & 15) << 2;
                cp_async16(sbase + (uint32_t)(row * FSTR + kg) * 4,
                           sc + (size_t)(m0 + row) * SEQL + t * BNT + kg);
            }
            uint32_t vbase = (uint32_t)__cvta_generic_to_shared(vs + st * BNT * FSTR);
            #pragma unroll
            for (int f = tid; f < BNT * DK / 4; f += 256) {
                int row = f >> 4;
                int kg  = (f & 15) << 2;
                cp_async16(vbase + (uint32_t)(row * FSTR + kg) * 4,
                           vp + (size_t)(t * BNT + row) * DK + kg);
            }
            cp_commit();
        };

        float acc[2][4][4];
        #pragma unroll
        for (int i = 0; i < 2; i++)
            #pragma unroll
            for (int j = 0; j < 4; j++)
                #pragma unroll
                for (int r = 0; r < 4; r++) acc[i][j][r] = 0.f;

        load_sv(0, NT - 1);
        cp_wait0();
        __syncthreads();

        int st = 0;
        for (int i = 0; i < NT; i++) {
            const int t = NT - 1 - i;
            if (t > 0) load_sv(st ^ 1, t - 1);

            // transform: w = exp(s)*inv; fp32 -> gmem weights, tf32 -> smem
            {
                float* Ssm = ss + st * BMA * FSTR;
                #pragma unroll
                for (int f = tid; f < BMA * BNT / 4; f += 256) {
                    int row = f >> 4;
                    int kg  = (f & 15) << 2;
                    float* p = &Ssm[row * FSTR + kg];
                    float inv = invs[row];
                    float w0 = __expf(p[0]) * inv;
                    float w1 = __expf(p[1]) * inv;
                    float w2 = __expf(p[2]) * inv;
                    float w3 = __expf(p[3]) * inv;
                    *reinterpret_cast<float4*>(
                        &wg[(size_t)(m0 + row) * SEQL + t * BNT + kg]) =
                        make_float4(w0, w1, w2, w3);
                    p[0] = tf32f(w0); p[1] = tf32f(w1);
                    p[2] = tf32f(w2); p[3] = tf32f(w3);
                }
            }
            __syncthreads();   // transformed smem visible to all warps

            // ctx += w[128x64] @ v[64x64]
            {
                const uint32_t sb = (uint32_t)__cvta_generic_to_shared(ss + st * BMA * FSTR);
                const float* __restrict__ Vsm = vs + st * BNT * FSTR;
                #pragma unroll
                for (int kk = 0; kk < BNT; kk += 8) {
                    const int kb = kk + (lane & 3);
                    uint32_t af[2][4];
                    #pragma unroll
                    for (int mm = 0; mm < 2; mm++)
                        ldsm_x4(af[mm], sb + (uint32_t)((wm + mm * 16 + arow) * FSTR + kk + acol) * 4);
                    uint32_t bf[4][2];
                    #pragma unroll
                    for (int nn = 0; nn < 4; nn++) {
                        int c = wn + nn * 8 + (lane >> 2);
                        bf[nn][0] = __float_as_uint(Vsm[kb * FSTR + c]);       // v pre-rounded
                        bf[nn][1] = __float_as_uint(Vsm[(kb + 4) * FSTR + c]);
                    }
                    #pragma unroll
                    for (int mm = 0; mm < 2; mm++)
                        #pragma unroll
                        for (int nn = 0; nn < 4; nn++)
                            mma_tf32(acc[mm][nn], af[mm], bf[nn]);
                }
            }

            cp_wait0();
            __syncthreads();
            st ^= 1;
        }

        // epilogue: ctx [b, s, (h d)], tf32-rounded for the out-GEMM
        const int b = z >> 4, h = z & (NH - 1);
        #pragma unroll
        for (int mm = 0; mm < 2; mm++)
            #pragma unroll
            for (int nn = 0; nn < 4; nn++)
                #pragma unroll
                for (int half = 0; half < 2; half++) {
                    int row = m0 + wm + mm * 16 + (lane >> 2) + half * 8;
                    int col = wn + nn * 8 + ((lane & 3) << 1);
                    *reinterpret_cast<float2*>(
                        &ctx[(size_t)(b * SEQL + row) * DMODEL + h * DK + col]) =
                        make_float2(tf32f(acc[mm][nn][half * 2 + 0]),
                                    tf32f(acc[mm][nn][half * 2 + 1]));
                }
    }
}

extern "C" void kernel_launch(void* const* d_in, const int* in_sizes, int n_in,
                              void* d_out, int out_size)
{
    const float* Q   = (const float*)d_in[0];
    const float* K   = (const float*)d_in[1];
    const float* V   = (const float*)d_in[2];
    const float* WQw = (const float*)d_in[3];
    const float* WQb = (const float*)d_in[4];
    const float* WKw = (const float*)d_in[5];
    const float* WKb = (const float*)d_in[6];
    const float* WVw = (const float*)d_in[7];
    const float* WVb = (const float*)d_in[8];
    const float* Wow = (const float*)d_in[9];
    const float* Wob = (const float*)d_in[10];

    float* out     = (float*)d_out;                              // [8,1024,1024]
    float* weights = out + (size_t)BSZ * SEQL * DMODEL;          // [8,16,1024,1024]
    float* scores  = weights + (size_t)BSZ * NH * SEQL * SEQL;   // [8,16,1024,1024]

    float *qp, *kp, *vp, *cp;
    float *rq, *rk, *rv, *rwq, *rwk, *rwv, *rwo;
    cudaGetSymbolAddress((void**)&qp, g_q);
    cudaGetSymbolAddress((void**)&kp, g_k);
    cudaGetSymbolAddress((void**)&vp, g_v);
    cudaGetSymbolAddress((void**)&cp, g_ctx);
    cudaGetSymbolAddress((void**)&rq, g_rq);
    cudaGetSymbolAddress((void**)&rk, g_rk);
    cudaGetSymbolAddress((void**)&rv, g_rv);
    cudaGetSymbolAddress((void**)&rwq, g_rwq);
    cudaGetSymbolAddress((void**)&rwk, g_rwk);
    cudaGetSymbolAddress((void**)&rwv, g_rwv);
    cudaGetSymbolAddress((void**)&rwo, g_rwo);

    const int M = BSZ * SEQL;  // 8192

    // Opt-in to >48KB dynamic smem for the fused attention kernel.
    static int smem_set = 0;
    if (!smem_set) {
        cudaFuncSetAttribute(attn_fused,
                             cudaFuncAttributeMaxDynamicSharedMemorySize, SM_TOTAL);
        smem_set = 1;
    }

    // Prep: tf32-round inputs; round+TRANSPOSE weights (for B-side LDSM)
    const int nx4 = (BSZ * SEQL * DMODEL) / 4;     // 2M float4
    round_copy<<<nx4 / 256, 256>>>((const float4*)Q, (float4*)rq, nx4);
    round_copy<<<nx4 / 256, 256>>>((const float4*)K, (float4*)rk, nx4);
    round_copy<<<nx4 / 256, 256>>>((const float4*)V, (float4*)rv, nx4);
    {
        dim3 tg(DMODEL / 32, DMODEL / 32);
        dim3 tb(32, 8);
        round_transpose<<<tg, tb>>>(WQw, rwq, DMODEL, DMODEL);
        round_transpose<<<tg, tb>>>(WKw, rwk, DMODEL, DMODEL);
        round_transpose<<<tg, tb>>>(WVw, rwv, DMODEL, DMODEL);
        round_transpose<<<tg, tb>>>(Wow, rwo, DMODEL, DMODEL);
    }

    // QKV projections -> [b,h,s,d]; q carries ATT_SCALE; outputs tf32-rounded
    gemm_big2<MODE_PROJ, true><<<dim3(DMODEL/128, M/128), 256>>>(rq, rwq, WQb, qp, M, DMODEL, DMODEL, ATT_SCALE);
    gemm_big2<MODE_PROJ, true><<<dim3(DMODEL/128, M/128), 256>>>(rk, rwk, WKb, kp, M, DMODEL, DMODEL, 1.0f);
    gemm_big2<MODE_PROJ, true><<<dim3(DMODEL/128, M/128), 256>>>(rv, rwv, WVb, vp, M, DMODEL, DMODEL, 1.0f);

    // Fused: scores + rowsum + softmax weights + ctx (scores re-read is L2-hot)
    attn_fused<<<dim3(1, SEQL / BMA, BSZ * NH), 256, SM_TOTAL>>>(
        qp, kp, vp, scores, weights, cp);

    // output = ctx @ Wo + b  (both operands pre-rounded; Wo transposed)
    gemm_big2<MODE_OUT, false><<<dim3(DMODEL/128, M/128), 256>>>(cp, rwo, Wob, out, M, DMODEL, DMODEL, 1.0f);
}